// round 3
// baseline (speedup 1.0000x reference)
#include <cuda_runtime.h>

// ---------------- problem constants ----------------
#define B_      16
#define N_      64
#define P_      6
#define D_      8
#define E_      128
#define H_      8
#define HD_     16
#define S_      512            // N*D tokens per batch
#define TOK_    (B_*S_)        // 8192
#define KVN_    (B_*2*S_)      // 16384
#define NPROTO_ 256            // D * 32 prototype rows
#define I_      64
#define O_      128
#define KOUT_   (S_*E_)        // 65536
#define KCHUNKS_ 128
#define KCSZ_   (KOUT_/KCHUNKS_) // 512

// ---------------- device scratch (no allocations allowed) ----------------
__device__ float g_PN  [NPROTO_*P_];
__device__ float g_PNL2[NPROTO_*P_];
__device__ float g_IE  [TOK_*E_];
__device__ float g_PE  [TOK_*E_];
__device__ float g_KV  [KVN_*E_];
__device__ float g_Q   [TOK_*E_];
__device__ float g_KVO [KVN_*2*E_];   // cols 0..127 = K, 128..255 = V
__device__ float g_AT  [TOK_*E_];
__device__ float g_AP  [TOK_*E_];
__device__ float g_H1  [TOK_*E_];
__device__ float g_F1  [TOK_*I_];
__device__ float g_F2  [TOK_*E_];
__device__ float g_Z   [TOK_*E_];
__device__ float g_PART[KCHUNKS_*B_*O_];

__device__ __forceinline__ float* bufptr(int id){
    switch(id){
        case 0: return g_IE;
        case 1: return g_KV;
        case 2: return g_Q;
        case 3: return g_KVO;
        case 4: return g_AT;
        case 5: return g_AP;
        case 6: return g_H1;
        case 7: return g_F1;
        case 8: return g_F2;
        default: return g_Z;
    }
}

// ---------------- prototype instance-norm + L2 ----------------
__global__ void k_proto(const float* __restrict__ proto){
    int t = threadIdx.x;
    if (t >= NPROTO_) return;
    float v[P_]; float s = 0.f;
    #pragma unroll
    for (int p = 0; p < P_; p++){ v[p] = proto[t*P_ + p]; s += v[p]; }
    float m = s * (1.f/P_);
    float var = 0.f;
    #pragma unroll
    for (int p = 0; p < P_; p++){ float d = v[p]-m; var += d*d; }
    var *= (1.f/P_);
    float rs = rsqrtf(var + 1e-5f);
    float nrm = 0.f;
    #pragma unroll
    for (int p = 0; p < P_; p++){ v[p] = (v[p]-m)*rs; nrm += v[p]*v[p]; g_PN[t*P_+p] = v[p]; }
    float inv = 1.f / fmaxf(sqrtf(nrm), 1e-12f);
    #pragma unroll
    for (int p = 0; p < P_; p++) g_PNL2[t*P_+p] = v[p]*inv;
}

// ---------------- per-row inorm + argmax lookup + both embeddings ----------------
// one warp per x-row (8192 rows); block = 8 warps
__global__ void k_rowprep(const float* __restrict__ x,
                          const float* __restrict__ Wemb, const float* __restrict__ bemb,
                          const float* __restrict__ Wpro, const float* __restrict__ bpro){
    __shared__ float sPN  [NPROTO_*P_];
    __shared__ float sPNL2[NPROTO_*P_];
    __shared__ float sWe[E_*P_];
    __shared__ float sWp[E_*P_];
    __shared__ float sbe[E_];
    __shared__ float sbp[E_];
    int tid = threadIdx.x;
    for (int i = tid; i < NPROTO_*P_; i += 256){ sPN[i] = g_PN[i]; sPNL2[i] = g_PNL2[i]; }
    for (int i = tid; i < E_*P_;     i += 256){ sWe[i] = Wemb[i];  sWp[i]  = Wpro[i]; }
    if (tid < E_){ sbe[tid] = bemb[tid]; sbp[tid] = bpro[tid]; }
    __syncthreads();

    int warp = tid >> 5, lane = tid & 31;
    int r = blockIdx.x*8 + warp;                 // 0..8191
    int b = r >> 9; int n = (r >> 3) & 63; int d = r & 7;
    const float* xp = x + ((b*64 + n)*6)*8 + d;  // stride D over p

    float v[6]; float s = 0.f;
    #pragma unroll
    for (int p = 0; p < 6; p++){ v[p] = xp[p*8]; s += v[p]; }
    float mean = s * (1.f/6.f);
    float var = 0.f;
    #pragma unroll
    for (int p = 0; p < 6; p++){ float dd = v[p]-mean; var += dd*dd; }
    var *= (1.f/6.f);
    float rs = rsqrtf(var + 1e-5f);
    float xn[6];
    #pragma unroll
    for (int p = 0; p < 6; p++) xn[p] = (v[p]-mean)*rs;

    // argmax over 256 prototypes (positive scale factor of xn irrelevant for argmax)
    float best = -1e30f; int bi = 0;
    #pragma unroll
    for (int i = 0; i < 8; i++){
        int pidx = i*32 + lane;
        const float* pr = &sPNL2[pidx*6];
        float sim = xn[0]*pr[0] + xn[1]*pr[1] + xn[2]*pr[2]
                  + xn[3]*pr[3] + xn[4]*pr[4] + xn[5]*pr[5];
        if (sim > best){ best = sim; bi = pidx; }
    }
    #pragma unroll
    for (int off = 16; off; off >>= 1){
        float ov = __shfl_xor_sync(0xffffffffu, best, off);
        int   oi = __shfl_xor_sync(0xffffffffu, bi,   off);
        if (ov > best || (ov == best && oi < bi)){ best = ov; bi = oi; }
    }

    float sel[6];
    #pragma unroll
    for (int p = 0; p < 6; p++) sel[p] = sPN[bi*6 + p];

    #pragma unroll
    for (int e4 = 0; e4 < 4; e4++){
        int e = e4*32 + lane;
        const float* we = &sWe[e*6];
        const float* wp = &sWp[e*6];
        float a1 = sbe[e], a2 = sbp[e];
        #pragma unroll
        for (int p = 0; p < 6; p++){ a1 += xn[p]*we[p]; a2 += sel[p]*wp[p]; }
        g_IE[r*E_ + e] = a1;
        g_PE[r*E_ + e] = a2;
    }
}

// ---------------- KV concat: [input_embed ; proto_embed] per batch ----------------
__global__ void k_concat(){
    int i = blockIdx.x*256 + threadIdx.x;        // float4 index, 524288 total
    int row = i >> 5; int c4 = i & 31;
    int b = row >> 10; int j = row & 1023;
    const float* base = (j < 512) ? g_IE : g_PE;
    const float4* src = (const float4*)(base + (b*512 + (j & 511))*E_);
    ((float4*)(g_KV + row*E_))[c4] = src[c4];
}

// ---------------- tiled SGEMM: C[M,N] = A[M,K] @ W[N,K]^T + bias ----------------
template<int RELU>
__global__ void k_sgemm(int aId, const float* __restrict__ W,
                        const float* __restrict__ bias, int cId,
                        int M, int Nn, int K){
    const float* A = bufptr(aId);
    float* C = bufptr(cId);
    __shared__ float As[16][68];
    __shared__ float Ws[16][68];
    int t  = threadIdx.x;
    int tx = t & 15, ty = t >> 4;
    int m0 = blockIdx.x * 64, n0 = blockIdx.y * 64;
    float c[4][4] = {};
    for (int k0 = 0; k0 < K; k0 += 16){
        #pragma unroll
        for (int i = 0; i < 4; i++){
            int e = t + i*256;
            int kL = e & 15, mL = e >> 4;
            As[kL][mL] = A[(m0+mL)*K + k0 + kL];
            Ws[kL][mL] = W[(n0+mL)*K + k0 + kL];
        }
        __syncthreads();
        #pragma unroll
        for (int kk = 0; kk < 16; kk++){
            float4 a  = *(const float4*)&As[kk][ty*4];
            float4 bb = *(const float4*)&Ws[kk][tx*4];
            float av[4] = {a.x, a.y, a.z, a.w};
            float bv[4] = {bb.x, bb.y, bb.z, bb.w};
            #pragma unroll
            for (int i = 0; i < 4; i++)
                #pragma unroll
                for (int j = 0; j < 4; j++)
                    c[i][j] += av[i]*bv[j];
        }
        __syncthreads();
    }
    float4 b4 = *(const float4*)&bias[n0 + tx*4];
    float bv[4] = {b4.x, b4.y, b4.z, b4.w};
    #pragma unroll
    for (int i = 0; i < 4; i++){
        int row = m0 + ty*4 + i;
        float4 o;
        o.x = c[i][0] + bv[0];
        o.y = c[i][1] + bv[1];
        o.z = c[i][2] + bv[2];
        o.w = c[i][3] + bv[3];
        if (RELU){
            o.x = fmaxf(o.x, 0.f); o.y = fmaxf(o.y, 0.f);
            o.z = fmaxf(o.z, 0.f); o.w = fmaxf(o.w, 0.f);
        }
        *(float4*)&C[row*Nn + n0 + tx*4] = o;
    }
}

// ---------------- attention: one q-row per thread, online softmax ----------------
__global__ void k_attn(){
    __shared__ float4 Ks[128][4];
    __shared__ float4 Vs[128][4];
    int bh = blockIdx.x >> 2, qt = blockIdx.x & 3;
    int b = bh >> 3, h = bh & 7;
    int tid = threadIdx.x;
    int t = qt*128 + tid;
    int qrow = b*512 + t;
    const float4* qp = (const float4*)(g_Q + qrow*E_ + h*16);
    float4 q0 = qp[0], q1 = qp[1], q2 = qp[2], q3 = qp[3];
    float m = -1e30f, l = 0.f;
    float o[16];
    #pragma unroll
    for (int e = 0; e < 16; e++) o[e] = 0.f;

    for (int jt = 0; jt < 8; jt++){
        int row = b*1024 + jt*128 + tid;
        const float4* kp = (const float4*)(g_KVO + (size_t)row*256 + h*16);
        const float4* vp = kp + 32;  // +128 floats
        #pragma unroll
        for (int i = 0; i < 4; i++){ Ks[tid][i] = kp[i]; Vs[tid][i] = vp[i]; }
        __syncthreads();
        #pragma unroll 4
        for (int jj = 0; jj < 128; jj++){
            float4 k0 = Ks[jj][0], k1 = Ks[jj][1], k2 = Ks[jj][2], k3 = Ks[jj][3];
            float s = q0.x*k0.x + q0.y*k0.y + q0.z*k0.z + q0.w*k0.w
                    + q1.x*k1.x + q1.y*k1.y + q1.z*k1.z + q1.w*k1.w
                    + q2.x*k2.x + q2.y*k2.y + q2.z*k2.z + q2.w*k2.w
                    + q3.x*k3.x + q3.y*k3.y + q3.z*k3.z + q3.w*k3.w;
            s *= 0.25f;
            float4 v0 = Vs[jj][0], v1 = Vs[jj][1], v2 = Vs[jj][2], v3 = Vs[jj][3];
            if (s <= m){
                float p = __expf(s - m);
                l += p;
                o[0]+=p*v0.x; o[1]+=p*v0.y; o[2]+=p*v0.z; o[3]+=p*v0.w;
                o[4]+=p*v1.x; o[5]+=p*v1.y; o[6]+=p*v1.z; o[7]+=p*v1.w;
                o[8]+=p*v2.x; o[9]+=p*v2.y; o[10]+=p*v2.z; o[11]+=p*v2.w;
                o[12]+=p*v3.x; o[13]+=p*v3.y; o[14]+=p*v3.z; o[15]+=p*v3.w;
            } else {
                float sc = __expf(m - s);
                m = s;
                l = l*sc + 1.f;
                o[0]=o[0]*sc+v0.x; o[1]=o[1]*sc+v0.y; o[2]=o[2]*sc+v0.z; o[3]=o[3]*sc+v0.w;
                o[4]=o[4]*sc+v1.x; o[5]=o[5]*sc+v1.y; o[6]=o[6]*sc+v1.z; o[7]=o[7]*sc+v1.w;
                o[8]=o[8]*sc+v2.x; o[9]=o[9]*sc+v2.y; o[10]=o[10]*sc+v2.z; o[11]=o[11]*sc+v2.w;
                o[12]=o[12]*sc+v3.x; o[13]=o[13]*sc+v3.y; o[14]=o[14]*sc+v3.z; o[15]=o[15]*sc+v3.w;
            }
        }
        __syncthreads();
    }
    float inv = 1.f / l;
    float4* op = (float4*)(g_AT + qrow*E_ + h*16);
    op[0] = make_float4(o[0]*inv,  o[1]*inv,  o[2]*inv,  o[3]*inv);
    op[1] = make_float4(o[4]*inv,  o[5]*inv,  o[6]*inv,  o[7]*inv);
    op[2] = make_float4(o[8]*inv,  o[9]*inv,  o[10]*inv, o[11]*inv);
    op[3] = make_float4(o[12]*inv, o[13]*inv, o[14]*inv, o[15]*inv);
}

// ---------------- residual + LayerNorm (row = 128) ----------------
__global__ void k_lnres(int aId, int rId, const float* __restrict__ g,
                        const float* __restrict__ be, int oId){
    const float* A = bufptr(aId);
    const float* R = bufptr(rId);
    float* out = bufptr(oId);
    int tid = threadIdx.x; int warp = tid >> 5, lane = tid & 31;
    int row = blockIdx.x*8 + warp;
    float v[4];
    #pragma unroll
    for (int i = 0; i < 4; i++){
        int e = i*32 + lane;
        v[i] = A[row*E_ + e] + R[row*E_ + e];
    }
    float s  = v[0]+v[1]+v[2]+v[3];
    float s2 = v[0]*v[0]+v[1]*v[1]+v[2]*v[2]+v[3]*v[3];
    #pragma unroll
    for (int off = 16; off; off >>= 1){
        s  += __shfl_xor_sync(0xffffffffu, s,  off);
        s2 += __shfl_xor_sync(0xffffffffu, s2, off);
    }
    float mean = s * (1.f/128.f);
    float var  = s2 * (1.f/128.f) - mean*mean;
    float rs = rsqrtf(var + 1e-5f);
    #pragma unroll
    for (int i = 0; i < 4; i++){
        int e = i*32 + lane;
        out[row*E_ + e] = (v[i]-mean)*rs*g[e] + be[e];
    }
}

// ---------------- final projection: split-K over 65536 ----------------
__global__ void k_splitk(const float* __restrict__ W){
    __shared__ float Zs[16*32];
    __shared__ float Ws_[32*129];
    int t = threadIdx.x;
    int kb = blockIdx.x * KCSZ_;
    int o = t & 127;
    int bset = t >> 7;
    float acc[8];
    #pragma unroll
    for (int i = 0; i < 8; i++) acc[i] = 0.f;
    for (int k0 = 0; k0 < KCSZ_; k0 += 32){
        #pragma unroll
        for (int i = 0; i < 2; i++){
            int e = t + i*256; int b_ = e >> 5, kk = e & 31;
            Zs[b_*32 + kk] = g_Z[(size_t)b_*KOUT_ + kb + k0 + kk];
        }
        #pragma unroll
        for (int i = 0; i < 16; i++){
            int e = t + i*256; int oo = e >> 5, kk = e & 31;
            Ws_[kk*129 + oo] = W[(size_t)oo*KOUT_ + kb + k0 + kk];
        }
        __syncthreads();
        #pragma unroll
        for (int kk = 0; kk < 32; kk++){
            float w = Ws_[kk*129 + o];
            #pragma unroll
            for (int i = 0; i < 8; i++)
                acc[i] += Zs[(bset*8 + i)*32 + kk] * w;
        }
        __syncthreads();
    }
    #pragma unroll
    for (int i = 0; i < 8; i++)
        g_PART[blockIdx.x*2048 + (bset*8 + i)*128 + o] = acc[i];
}

__global__ void k_reduce(const float* __restrict__ bout, float* __restrict__ out){
    int e = blockIdx.x*256 + threadIdx.x;   // 0..2047
    float s = bout[e & 127];
    #pragma unroll 8
    for (int c = 0; c < KCHUNKS_; c++) s += g_PART[c*2048 + e];
    out[e] = s;
}

// ---------------- launch ----------------
extern "C" void kernel_launch(void* const* d_in, const int* in_sizes, int n_in,
                              void* d_out, int out_size){
    const float* x    = (const float*)d_in[0];
    const float* prot = (const float*)d_in[1];
    const float* Wemb = (const float*)d_in[2];
    const float* bemb = (const float*)d_in[3];
    const float* Wpro = (const float*)d_in[4];
    const float* bpro = (const float*)d_in[5];
    const float* inw  = (const float*)d_in[6];
    const float* inb  = (const float*)d_in[7];
    const float* ow   = (const float*)d_in[8];
    const float* ob   = (const float*)d_in[9];
    const float* W1   = (const float*)d_in[10];
    const float* b1   = (const float*)d_in[11];
    const float* W2   = (const float*)d_in[12];
    const float* b2   = (const float*)d_in[13];
    const float* g1   = (const float*)d_in[14];
    const float* be1  = (const float*)d_in[15];
    const float* g2   = (const float*)d_in[16];
    const float* be2  = (const float*)d_in[17];
    const float* Wout = (const float*)d_in[18];
    const float* bout = (const float*)d_in[19];
    float* out = (float*)d_out;

    // 1. prototype norms
    k_proto<<<1, 256>>>(prot);
    // 2. inorm + argmax + embeddings
    k_rowprep<<<1024, 256>>>(x, Wemb, bemb, Wpro, bpro);
    // 3. Q projection: IE(0) -> Q(2)
    k_sgemm<0><<<dim3(TOK_/64, E_/64), 256>>>(0, inw, inb, 2, TOK_, E_, E_);
    // 4. KV concat
    k_concat<<<2048, 256>>>();
    // 5. fused K|V projection: KV(1) -> KVO(3), N=256 using rows 128..383 of in_proj
    k_sgemm<0><<<dim3(KVN_/64, 256/64), 256>>>(1, inw + 128*E_, inb + 128, 3, KVN_, 256, E_);
    // 6. attention
    k_attn<<<B_*H_*4, 128>>>();
    // 7. out_proj: AT(4) -> AP(5)
    k_sgemm<0><<<dim3(TOK_/64, E_/64), 256>>>(4, ow, ob, 5, TOK_, E_, E_);
    // 8. h1 = LN(IE + AP)
    k_lnres<<<TOK_/8, 256>>>(0, 5, g1, be1, 6);
    // 9. ffn1 = relu(h1 @ W1^T + b1): H1(6) -> F1(7)
    k_sgemm<1><<<dim3(TOK_/64, I_/64), 256>>>(6, W1, b1, 7, TOK_, I_, E_);
    // 10. ffn2: F1(7) -> F2(8)
    k_sgemm<0><<<dim3(TOK_/64, E_/64), 256>>>(7, W2, b2, 8, TOK_, E_, I_);
    // 11. z = LN(h1 + ffn2)
    k_lnres<<<TOK_/8, 256>>>(6, 8, g2, be2, 9);
    // 12. final projection split-K + reduce
    k_splitk<<<KCHUNKS_, 256>>>(Wout);
    k_reduce<<<8, 256>>>(bout, out);
}

// round 4
// speedup vs baseline: 1.3517x; 1.3517x over previous
#include <cuda_runtime.h>

// ---------------- problem constants ----------------
#define B_      16
#define N_      64
#define P_      6
#define D_      8
#define E_      128
#define H_      8
#define HD_     16
#define S_      512            // N*D tokens per batch
#define TOK_    (B_*S_)        // 8192
#define KVN_    (B_*2*S_)      // 16384
#define NPROTO_ 256            // D * 32 prototype rows
#define I_      64
#define O_      128
#define KOUT_   (S_*E_)        // 65536
#define KCHUNKS_ 128
#define KCSZ_   (KOUT_/KCHUNKS_) // 512

// ---------------- device scratch (no allocations allowed) ----------------
__device__ float g_PN  [NPROTO_*P_];
__device__ float g_PNL2[NPROTO_*P_];
__device__ float g_IE  [TOK_*E_];
__device__ float g_PE  [TOK_*E_];
__device__ float g_Q   [TOK_*E_];
__device__ float g_KVO [KVN_*2*E_];   // cols 0..127 = K, 128..255 = V
__device__ float g_AT  [TOK_*E_];
__device__ float g_AP  [TOK_*E_];
__device__ float g_H1  [TOK_*E_];
__device__ float g_F1  [TOK_*I_];
__device__ float g_F2  [TOK_*E_];
__device__ float g_Z   [TOK_*E_];
__device__ float g_PART[KCHUNKS_*B_*O_];
__device__ float g_QN  [TOK_*H_];     // per (qrow, head) L2 norm
__device__ float g_KMAX[B_*H_];       // per (b, head) max key L2 norm

__device__ __forceinline__ float* bufptr(int id){
    switch(id){
        case 0: return g_IE;
        case 2: return g_Q;
        case 3: return g_KVO;
        case 4: return g_AT;
        case 5: return g_AP;
        case 6: return g_H1;
        case 7: return g_F1;
        case 8: return g_F2;
        default: return g_Z;
    }
}

// ---------------- tf32 helpers ----------------
__device__ __forceinline__ unsigned f2tf(float f){
    unsigned r; asm("cvt.rna.tf32.f32 %0, %1;" : "=r"(r) : "f"(f)); return r;
}
__device__ __forceinline__ void mma_tf32(float c[4], const unsigned a[4], const unsigned b[2]){
    asm volatile("mma.sync.aligned.m16n8k8.row.col.f32.tf32.tf32.f32 "
        "{%0,%1,%2,%3}, {%4,%5,%6,%7}, {%8,%9}, {%0,%1,%2,%3};"
        : "+f"(c[0]), "+f"(c[1]), "+f"(c[2]), "+f"(c[3])
        : "r"(a[0]), "r"(a[1]), "r"(a[2]), "r"(a[3]), "r"(b[0]), "r"(b[1]));
}

// ---------------- prototype instance-norm + L2 ----------------
__global__ void k_proto(const float* __restrict__ proto){
    int t = threadIdx.x;
    if (t >= NPROTO_) return;
    float v[P_]; float s = 0.f;
    #pragma unroll
    for (int p = 0; p < P_; p++){ v[p] = proto[t*P_ + p]; s += v[p]; }
    float m = s * (1.f/P_);
    float var = 0.f;
    #pragma unroll
    for (int p = 0; p < P_; p++){ float d = v[p]-m; var += d*d; }
    var *= (1.f/P_);
    float rs = rsqrtf(var + 1e-5f);
    float nrm = 0.f;
    #pragma unroll
    for (int p = 0; p < P_; p++){ v[p] = (v[p]-m)*rs; nrm += v[p]*v[p]; g_PN[t*P_+p] = v[p]; }
    float inv = 1.f / fmaxf(sqrtf(nrm), 1e-12f);
    #pragma unroll
    for (int p = 0; p < P_; p++) g_PNL2[t*P_+p] = v[p]*inv;
}

// ---------------- per-row inorm + argmax lookup + both embeddings ----------------
__global__ void k_rowprep(const float* __restrict__ x,
                          const float* __restrict__ Wemb, const float* __restrict__ bemb,
                          const float* __restrict__ Wpro, const float* __restrict__ bpro){
    __shared__ float sPN  [NPROTO_*P_];
    __shared__ float sPNL2[NPROTO_*P_];
    __shared__ float sWe[E_*P_];
    __shared__ float sWp[E_*P_];
    __shared__ float sbe[E_];
    __shared__ float sbp[E_];
    int tid = threadIdx.x;
    for (int i = tid; i < NPROTO_*P_; i += 256){ sPN[i] = g_PN[i]; sPNL2[i] = g_PNL2[i]; }
    for (int i = tid; i < E_*P_;     i += 256){ sWe[i] = Wemb[i];  sWp[i]  = Wpro[i]; }
    if (tid < E_){ sbe[tid] = bemb[tid]; sbp[tid] = bpro[tid]; }
    __syncthreads();

    int warp = tid >> 5, lane = tid & 31;
    int r = blockIdx.x*8 + warp;
    int b = r >> 9; int n = (r >> 3) & 63; int d = r & 7;
    const float* xp = x + ((b*64 + n)*6)*8 + d;

    float v[6]; float s = 0.f;
    #pragma unroll
    for (int p = 0; p < 6; p++){ v[p] = xp[p*8]; s += v[p]; }
    float mean = s * (1.f/6.f);
    float var = 0.f;
    #pragma unroll
    for (int p = 0; p < 6; p++){ float dd = v[p]-mean; var += dd*dd; }
    var *= (1.f/6.f);
    float rs = rsqrtf(var + 1e-5f);
    float xn[6];
    #pragma unroll
    for (int p = 0; p < 6; p++) xn[p] = (v[p]-mean)*rs;

    float best = -1e30f; int bi = 0;
    #pragma unroll
    for (int i = 0; i < 8; i++){
        int pidx = i*32 + lane;
        const float* pr = &sPNL2[pidx*6];
        float sim = xn[0]*pr[0] + xn[1]*pr[1] + xn[2]*pr[2]
                  + xn[3]*pr[3] + xn[4]*pr[4] + xn[5]*pr[5];
        if (sim > best){ best = sim; bi = pidx; }
    }
    #pragma unroll
    for (int off = 16; off; off >>= 1){
        float ov = __shfl_xor_sync(0xffffffffu, best, off);
        int   oi = __shfl_xor_sync(0xffffffffu, bi,   off);
        if (ov > best || (ov == best && oi < bi)){ best = ov; bi = oi; }
    }

    float sel[6];
    #pragma unroll
    for (int p = 0; p < 6; p++) sel[p] = sPN[bi*6 + p];

    #pragma unroll
    for (int e4 = 0; e4 < 4; e4++){
        int e = e4*32 + lane;
        const float* we = &sWe[e*6];
        const float* wp = &sWp[e*6];
        float a1 = sbe[e], a2 = sbp[e];
        #pragma unroll
        for (int p = 0; p < 6; p++){ a1 += xn[p]*we[p]; a2 += sel[p]*wp[p]; }
        g_IE[r*E_ + e] = a1;
        g_PE[r*E_ + e] = a2;
    }
}

// ---------------- tiled SGEMM: C[M,N] = A[M,K] @ W[N,K]^T + bias ----------------
// CONCAT=1: A rows follow the [IE;PE] per-batch concat layout (virtual KV matrix)
template<int RELU, int CONCAT>
__global__ void k_sgemm(int aId, const float* __restrict__ W,
                        const float* __restrict__ bias, int cId,
                        int M, int Nn, int K){
    float* C = bufptr(cId);
    __shared__ float As[16][68];
    __shared__ float Ws[16][68];
    int t  = threadIdx.x;
    int tx = t & 15, ty = t >> 4;
    int m0 = blockIdx.x * 64, n0 = blockIdx.y * 64;
    const float* Abase;
    if (CONCAT){
        int bb = m0 >> 10, j = m0 & 1023;
        Abase = ((j < 512) ? g_IE : g_PE) + (size_t)(bb*512 + (j & 511)) * K;
    } else {
        Abase = bufptr(aId) + (size_t)m0 * K;
    }
    float c[4][4] = {};
    for (int k0 = 0; k0 < K; k0 += 16){
        #pragma unroll
        for (int i = 0; i < 4; i++){
            int e = t + i*256;
            int kL = e & 15, mL = e >> 4;
            As[kL][mL] = Abase[mL*K + k0 + kL];
            Ws[kL][mL] = W[(n0+mL)*K + k0 + kL];
        }
        __syncthreads();
        #pragma unroll
        for (int kk = 0; kk < 16; kk++){
            float4 a  = *(const float4*)&As[kk][ty*4];
            float4 bb = *(const float4*)&Ws[kk][tx*4];
            float av[4] = {a.x, a.y, a.z, a.w};
            float bv[4] = {bb.x, bb.y, bb.z, bb.w};
            #pragma unroll
            for (int i = 0; i < 4; i++)
                #pragma unroll
                for (int j = 0; j < 4; j++)
                    c[i][j] += av[i]*bv[j];
        }
        __syncthreads();
    }
    float4 b4 = *(const float4*)&bias[n0 + tx*4];
    float bv[4] = {b4.x, b4.y, b4.z, b4.w};
    #pragma unroll
    for (int i = 0; i < 4; i++){
        int row = m0 + ty*4 + i;
        float4 o;
        o.x = c[i][0] + bv[0];
        o.y = c[i][1] + bv[1];
        o.z = c[i][2] + bv[2];
        o.w = c[i][3] + bv[3];
        if (RELU){
            o.x = fmaxf(o.x, 0.f); o.y = fmaxf(o.y, 0.f);
            o.z = fmaxf(o.z, 0.f); o.w = fmaxf(o.w, 0.f);
        }
        *(float4*)&C[(size_t)row*Nn + n0 + tx*4] = o;
    }
}

// ---------------- per (qrow, head) L2 norm of q ----------------
__global__ void k_qn(){
    int i = blockIdx.x*256 + threadIdx.x;      // 0..65535 = row*8+h
    int row = i >> 3, h = i & 7;
    const float4* q = (const float4*)(g_Q + (size_t)row*E_ + h*16);
    float4 a = q[0], b = q[1], c = q[2], d = q[3];
    float s = a.x*a.x+a.y*a.y+a.z*a.z+a.w*a.w
            + b.x*b.x+b.y*b.y+b.z*b.z+b.w*b.w
            + c.x*c.x+c.y*c.y+c.z*c.z+c.w*c.w
            + d.x*d.x+d.y*d.y+d.z*d.z+d.w*d.w;
    g_QN[i] = sqrtf(s);
}

// ---------------- per (b, head) max key L2 norm ----------------
__global__ void k_kmax(){
    int bh = blockIdx.x; int b = bh >> 3, h = bh & 7;
    const float* base = g_KVO + (size_t)(b*1024)*256 + h*16;
    float mx = 0.f;
    for (int j = threadIdx.x; j < 1024; j += 256){
        const float4* kp = (const float4*)(base + (size_t)j*256);
        float4 a = kp[0], bb = kp[1], c = kp[2], d = kp[3];
        float s = a.x*a.x+a.y*a.y+a.z*a.z+a.w*a.w
                + bb.x*bb.x+bb.y*bb.y+bb.z*bb.z+bb.w*bb.w
                + c.x*c.x+c.y*c.y+c.z*c.z+c.w*c.w
                + d.x*d.x+d.y*d.y+d.z*d.z+d.w*d.w;
        mx = fmaxf(mx, s);
    }
    #pragma unroll
    for (int off = 16; off; off >>= 1)
        mx = fmaxf(mx, __shfl_xor_sync(0xffffffffu, mx, off));
    __shared__ float red[8];
    if ((threadIdx.x & 31) == 0) red[threadIdx.x >> 5] = mx;
    __syncthreads();
    if (threadIdx.x == 0){
        float m = red[0];
        #pragma unroll
        for (int w = 1; w < 8; w++) m = fmaxf(m, red[w]);
        g_KMAX[bh] = sqrtf(m);
    }
}

// ---------------- attention with tf32 mma: bound-shifted single-pass softmax ----
// grid = B*H*2 blocks; block = 128 threads (4 warps); warp handles 64 q rows.
__global__ void __launch_bounds__(128) k_attn(){
    int blk = blockIdx.x;                 // 0..255
    int bh = blk >> 1, qh = blk & 1;
    int b = bh >> 3, h = bh & 7;
    int lane = threadIdx.x & 31, warp = threadIdx.x >> 5;
    int lq = lane >> 2, lc = lane & 3;
    int qrow0 = b*512 + qh*256 + warp*64; // 64 q rows for this warp
    int hoff = h*16;
    const float* Qb  = g_Q  + (size_t)qrow0*E_ + hoff;
    const float* KVb = g_KVO + (size_t)(b*1024)*256;

    // Q A-fragments: [mt][kstep][reg]
    unsigned qa[4][2][4];
    #pragma unroll
    for (int mt = 0; mt < 4; mt++)
        #pragma unroll
        for (int ks = 0; ks < 2; ks++){
            const float* qp = Qb + (size_t)(mt*16)*E_ + ks*8;
            qa[mt][ks][0] = f2tf(qp[(size_t)lq*E_     + lc]);
            qa[mt][ks][1] = f2tf(qp[(size_t)(lq+8)*E_ + lc]);
            qa[mt][ks][2] = f2tf(qp[(size_t)lq*E_     + lc+4]);
            qa[mt][ks][3] = f2tf(qp[(size_t)(lq+8)*E_ + lc+4]);
        }

    // score upper bounds per row: mb = ||q|| * max||k|| / 4
    float kmax = g_KMAX[bh];
    float mb[4][2];
    #pragma unroll
    for (int mt = 0; mt < 4; mt++){
        mb[mt][0] = g_QN[(qrow0 + mt*16 + lq  )*8 + h] * kmax * 0.25f;
        mb[mt][1] = g_QN[(qrow0 + mt*16 + lq+8)*8 + h] * kmax * 0.25f;
    }

    float o[4][2][4];
    #pragma unroll
    for (int mt = 0; mt < 4; mt++)
        #pragma unroll
        for (int d = 0; d < 2; d++)
            o[mt][d][0]=o[mt][d][1]=o[mt][d][2]=o[mt][d][3]=0.f;
    float lsum[4][2] = {};

    int s1 = (lane & 28) | (lc >> 1);
    int s2 = s1 + 2;
    bool odd = lc & 1;

    #pragma unroll 1
    for (int key0 = 0; key0 < 1024; key0 += 16){
        // K B-fragments (QK^T): [ntile][kstep][reg]
        unsigned kb[2][2][2];
        const float* kbase = KVb + (size_t)key0*256 + hoff;
        #pragma unroll
        for (int nt = 0; nt < 2; nt++)
            #pragma unroll
            for (int ks = 0; ks < 2; ks++){
                const float* kp = kbase + (size_t)(nt*8 + lq)*256 + ks*8 + lc;
                kb[nt][ks][0] = f2tf(kp[0]);
                kb[nt][ks][1] = f2tf(kp[4]);
            }
        // scores
        float s[4][2][4];
        #pragma unroll
        for (int mt = 0; mt < 4; mt++)
            #pragma unroll
            for (int nt = 0; nt < 2; nt++){
                s[mt][nt][0]=s[mt][nt][1]=s[mt][nt][2]=s[mt][nt][3]=0.f;
                mma_tf32(s[mt][nt], qa[mt][0], kb[nt][0]);
                mma_tf32(s[mt][nt], qa[mt][1], kb[nt][1]);
            }
        // p = exp(s/4 - mb), tf32-rounded; accumulate row sums
        #pragma unroll
        for (int mt = 0; mt < 4; mt++)
            #pragma unroll
            for (int nt = 0; nt < 2; nt++){
                float p0 = __expf(s[mt][nt][0]*0.25f - mb[mt][0]);
                float p1 = __expf(s[mt][nt][1]*0.25f - mb[mt][0]);
                float p2 = __expf(s[mt][nt][2]*0.25f - mb[mt][1]);
                float p3 = __expf(s[mt][nt][3]*0.25f - mb[mt][1]);
                float q0 = __uint_as_float(f2tf(p0));
                float q1 = __uint_as_float(f2tf(p1));
                float q2 = __uint_as_float(f2tf(p2));
                float q3 = __uint_as_float(f2tf(p3));
                s[mt][nt][0]=q0; s[mt][nt][1]=q1; s[mt][nt][2]=q2; s[mt][nt][3]=q3;
                lsum[mt][0] += q0 + q1;
                lsum[mt][1] += q2 + q3;
            }
        // V B-fragments (P@V): [kstep][dtile][reg]
        unsigned vb[2][2][2];
        const float* vbase = KVb + (size_t)key0*256 + 128 + hoff;
        #pragma unroll
        for (int kt = 0; kt < 2; kt++)
            #pragma unroll
            for (int d = 0; d < 2; d++){
                const float* vp = vbase + (size_t)(kt*8 + lc)*256 + d*8 + lq;
                vb[kt][d][0] = f2tf(vp[0]);
                vb[kt][d][1] = f2tf(vp[4*256]);
            }
        // P·V, converting C-frag layout to A-frag layout via shuffles
        #pragma unroll
        for (int mt = 0; mt < 4; mt++)
            #pragma unroll
            for (int kt = 0; kt < 2; kt++){
                unsigned a[4];
                float w0 = __shfl_sync(0xffffffffu, s[mt][kt][0], s1);
                float w1 = __shfl_sync(0xffffffffu, s[mt][kt][1], s1);
                a[0] = __float_as_uint(odd ? w1 : w0);
                float w2 = __shfl_sync(0xffffffffu, s[mt][kt][2], s1);
                float w3 = __shfl_sync(0xffffffffu, s[mt][kt][3], s1);
                a[1] = __float_as_uint(odd ? w3 : w2);
                w0 = __shfl_sync(0xffffffffu, s[mt][kt][0], s2);
                w1 = __shfl_sync(0xffffffffu, s[mt][kt][1], s2);
                a[2] = __float_as_uint(odd ? w1 : w0);
                w2 = __shfl_sync(0xffffffffu, s[mt][kt][2], s2);
                w3 = __shfl_sync(0xffffffffu, s[mt][kt][3], s2);
                a[3] = __float_as_uint(odd ? w3 : w2);
                mma_tf32(o[mt][0], a, vb[kt][0]);
                mma_tf32(o[mt][1], a, vb[kt][1]);
            }
    }

    // finalize: full row sums via quad reduce, then normalize + store
    float inv[4][2];
    #pragma unroll
    for (int mt = 0; mt < 4; mt++)
        #pragma unroll
        for (int hf = 0; hf < 2; hf++){
            float l = lsum[mt][hf];
            l += __shfl_xor_sync(0xffffffffu, l, 1);
            l += __shfl_xor_sync(0xffffffffu, l, 2);
            inv[mt][hf] = 1.f / l;
        }
    #pragma unroll
    for (int mt = 0; mt < 4; mt++)
        #pragma unroll
        for (int d = 0; d < 2; d++){
            float* op = g_AT + (size_t)(qrow0 + mt*16 + lq)*E_ + hoff + d*8 + 2*lc;
            *(float2*)op = make_float2(o[mt][d][0]*inv[mt][0], o[mt][d][1]*inv[mt][0]);
            *(float2*)(op + 8*E_) = make_float2(o[mt][d][2]*inv[mt][1], o[mt][d][3]*inv[mt][1]);
        }
}

// ---------------- residual + LayerNorm (row = 128) ----------------
__global__ void k_lnres(int aId, int rId, const float* __restrict__ g,
                        const float* __restrict__ be, int oId){
    const float* A = bufptr(aId);
    const float* R = bufptr(rId);
    float* out = bufptr(oId);
    int tid = threadIdx.x; int warp = tid >> 5, lane = tid & 31;
    int row = blockIdx.x*8 + warp;
    float v[4];
    #pragma unroll
    for (int i = 0; i < 4; i++){
        int e = i*32 + lane;
        v[i] = A[(size_t)row*E_ + e] + R[(size_t)row*E_ + e];
    }
    float s  = v[0]+v[1]+v[2]+v[3];
    float s2 = v[0]*v[0]+v[1]*v[1]+v[2]*v[2]+v[3]*v[3];
    #pragma unroll
    for (int off = 16; off; off >>= 1){
        s  += __shfl_xor_sync(0xffffffffu, s,  off);
        s2 += __shfl_xor_sync(0xffffffffu, s2, off);
    }
    float mean = s * (1.f/128.f);
    float var  = s2 * (1.f/128.f) - mean*mean;
    float rs = rsqrtf(var + 1e-5f);
    #pragma unroll
    for (int i = 0; i < 4; i++){
        int e = i*32 + lane;
        out[(size_t)row*E_ + e] = (v[i]-mean)*rs*g[e] + be[e];
    }
}

// ---------------- final projection: split-K over 65536 ----------------
__global__ void k_splitk(const float* __restrict__ W){
    __shared__ float Zs[16*32];
    __shared__ float Ws_[32*129];
    int t = threadIdx.x;
    int kb = blockIdx.x * KCSZ_;
    int o = t & 127;
    int bset = t >> 7;
    float acc[8];
    #pragma unroll
    for (int i = 0; i < 8; i++) acc[i] = 0.f;
    for (int k0 = 0; k0 < KCSZ_; k0 += 32){
        #pragma unroll
        for (int i = 0; i < 2; i++){
            int e = t + i*256; int b_ = e >> 5, kk = e & 31;
            Zs[b_*32 + kk] = g_Z[(size_t)b_*KOUT_ + kb + k0 + kk];
        }
        #pragma unroll
        for (int i = 0; i < 16; i++){
            int e = t + i*256; int oo = e >> 5, kk = e & 31;
            Ws_[kk*129 + oo] = W[(size_t)oo*KOUT_ + kb + k0 + kk];
        }
        __syncthreads();
        #pragma unroll
        for (int kk = 0; kk < 32; kk++){
            float w = Ws_[kk*129 + o];
            #pragma unroll
            for (int i = 0; i < 8; i++)
                acc[i] += Zs[(bset*8 + i)*32 + kk] * w;
        }
        __syncthreads();
    }
    #pragma unroll
    for (int i = 0; i < 8; i++)
        g_PART[blockIdx.x*2048 + (bset*8 + i)*128 + o] = acc[i];
}

__global__ void k_reduce(const float* __restrict__ bout, float* __restrict__ out){
    int e = blockIdx.x*256 + threadIdx.x;   // 0..2047
    float s = bout[e & 127];
    #pragma unroll 8
    for (int c = 0; c < KCHUNKS_; c++) s += g_PART[c*2048 + e];
    out[e] = s;
}

// ---------------- launch ----------------
extern "C" void kernel_launch(void* const* d_in, const int* in_sizes, int n_in,
                              void* d_out, int out_size){
    const float* x    = (const float*)d_in[0];
    const float* prot = (const float*)d_in[1];
    const float* Wemb = (const float*)d_in[2];
    const float* bemb = (const float*)d_in[3];
    const float* Wpro = (const float*)d_in[4];
    const float* bpro = (const float*)d_in[5];
    const float* inw  = (const float*)d_in[6];
    const float* inb  = (const float*)d_in[7];
    const float* ow   = (const float*)d_in[8];
    const float* ob   = (const float*)d_in[9];
    const float* W1   = (const float*)d_in[10];
    const float* b1   = (const float*)d_in[11];
    const float* W2   = (const float*)d_in[12];
    const float* b2   = (const float*)d_in[13];
    const float* g1   = (const float*)d_in[14];
    const float* be1  = (const float*)d_in[15];
    const float* g2   = (const float*)d_in[16];
    const float* be2  = (const float*)d_in[17];
    const float* Wout = (const float*)d_in[18];
    const float* bout = (const float*)d_in[19];
    float* out = (float*)d_out;

    // 1. prototype norms
    k_proto<<<1, 256>>>(prot);
    // 2. inorm + argmax + embeddings
    k_rowprep<<<1024, 256>>>(x, Wemb, bemb, Wpro, bpro);
    // 3. Q projection: IE(0) -> Q(2)
    k_sgemm<0,0><<<dim3(TOK_/64, E_/64), 256>>>(0, inw, inb, 2, TOK_, E_, E_);
    // 4. fused K|V projection with virtual [IE;PE] concat -> KVO(3)
    k_sgemm<0,1><<<dim3(KVN_/64, 256/64), 256>>>(0, inw + 128*E_, inb + 128, 3, KVN_, 256, E_);
    // 5. softmax bound prep
    k_qn<<<TOK_*H_/256, 256>>>();
    k_kmax<<<B_*H_, 256>>>();
    // 6. attention (tf32 tensor cores)
    k_attn<<<B_*H_*2, 128>>>();
    // 7. out_proj: AT(4) -> AP(5)
    k_sgemm<0,0><<<dim3(TOK_/64, E_/64), 256>>>(4, ow, ob, 5, TOK_, E_, E_);
    // 8. h1 = LN(IE + AP)
    k_lnres<<<TOK_/8, 256>>>(0, 5, g1, be1, 6);
    // 9. ffn1 = relu(h1 @ W1^T + b1): H1(6) -> F1(7)
    k_sgemm<1,0><<<dim3(TOK_/64, I_/64), 256>>>(6, W1, b1, 7, TOK_, I_, E_);
    // 10. ffn2: F1(7) -> F2(8)
    k_sgemm<0,0><<<dim3(TOK_/64, E_/64), 256>>>(7, W2, b2, 8, TOK_, E_, I_);
    // 11. z = LN(h1 + ffn2)
    k_lnres<<<TOK_/8, 256>>>(6, 8, g2, be2, 9);
    // 12. final projection split-K + reduce
    k_splitk<<<KCHUNKS_, 256>>>(Wout);
    k_reduce<<<8, 256>>>(bout, out);
}

// round 5
// speedup vs baseline: 1.5322x; 1.1335x over previous
#include <cuda_runtime.h>

// ---------------- problem constants ----------------
#define B_      16
#define N_      64
#define P_      6
#define D_      8
#define E_      128
#define H_      8
#define HD_     16
#define S_      512            // N*D tokens per batch
#define TOK_    (B_*S_)        // 8192
#define KVN_    (B_*2*S_)      // 16384
#define NPROTO_ 256            // D * 32 prototype rows
#define I_      64
#define O_      128
#define KOUT_   (S_*E_)        // 65536
#define KCHUNKS_ 128
#define KCSZ_   (KOUT_/KCHUNKS_) // 512

// ---------------- device scratch (no allocations allowed) ----------------
__device__ float g_PN  [NPROTO_*P_];
__device__ float g_PNL2[NPROTO_*P_];
__device__ float g_IE  [TOK_*E_];
__device__ float g_PE  [TOK_*E_];
__device__ float g_Q   [TOK_*E_];
__device__ float g_KVO [KVN_*2*E_];   // cols 0..127 = K, 128..255 = V
__device__ float g_AT  [TOK_*E_];
__device__ float g_AP  [TOK_*E_];
__device__ float g_H1  [TOK_*E_];
__device__ float g_F1  [TOK_*I_];
__device__ float g_F2  [TOK_*E_];
__device__ float g_Z   [TOK_*E_];
__device__ float g_PART[KCHUNKS_*B_*O_];
__device__ float g_QN  [TOK_*H_];     // per (qrow, head) L2 norm
__device__ float g_KMAX[B_*H_];       // per (b, head) max key L2 norm

__device__ __forceinline__ float* bufptr(int id){
    switch(id){
        case 0: return g_IE;
        case 2: return g_Q;
        case 3: return g_KVO;
        case 4: return g_AT;
        case 5: return g_AP;
        case 6: return g_H1;
        case 7: return g_F1;
        case 8: return g_F2;
        default: return g_Z;
    }
}

// ---------------- tf32 helpers ----------------
__device__ __forceinline__ unsigned f2tf(float f){
    unsigned r; asm("cvt.rna.tf32.f32 %0, %1;" : "=r"(r) : "f"(f)); return r;
}
__device__ __forceinline__ void mma_tf32(float c[4], const unsigned a[4], const unsigned b[2]){
    asm volatile("mma.sync.aligned.m16n8k8.row.col.f32.tf32.tf32.f32 "
        "{%0,%1,%2,%3}, {%4,%5,%6,%7}, {%8,%9}, {%0,%1,%2,%3};"
        : "+f"(c[0]), "+f"(c[1]), "+f"(c[2]), "+f"(c[3])
        : "r"(a[0]), "r"(a[1]), "r"(a[2]), "r"(a[3]), "r"(b[0]), "r"(b[1]));
}

// ---------------- prototype instance-norm + L2 ----------------
__global__ void k_proto(const float* __restrict__ proto){
    int t = threadIdx.x;
    if (t >= NPROTO_) return;
    float v[P_]; float s = 0.f;
    #pragma unroll
    for (int p = 0; p < P_; p++){ v[p] = proto[t*P_ + p]; s += v[p]; }
    float m = s * (1.f/P_);
    float var = 0.f;
    #pragma unroll
    for (int p = 0; p < P_; p++){ float d = v[p]-m; var += d*d; }
    var *= (1.f/P_);
    float rs = rsqrtf(var + 1e-5f);
    float nrm = 0.f;
    #pragma unroll
    for (int p = 0; p < P_; p++){ v[p] = (v[p]-m)*rs; nrm += v[p]*v[p]; g_PN[t*P_+p] = v[p]; }
    float inv = 1.f / fmaxf(sqrtf(nrm), 1e-12f);
    #pragma unroll
    for (int p = 0; p < P_; p++) g_PNL2[t*P_+p] = v[p]*inv;
}

// ---------------- per-row inorm + argmax lookup + both embeddings ----------------
__global__ void k_rowprep(const float* __restrict__ x,
                          const float* __restrict__ Wemb, const float* __restrict__ bemb,
                          const float* __restrict__ Wpro, const float* __restrict__ bpro){
    __shared__ float sPN  [NPROTO_*P_];
    __shared__ float sPNL2[NPROTO_*P_];
    __shared__ float sWe[E_*P_];
    __shared__ float sWp[E_*P_];
    __shared__ float sbe[E_];
    __shared__ float sbp[E_];
    int tid = threadIdx.x;
    for (int i = tid; i < NPROTO_*P_; i += 256){ sPN[i] = g_PN[i]; sPNL2[i] = g_PNL2[i]; }
    for (int i = tid; i < E_*P_;     i += 256){ sWe[i] = Wemb[i];  sWp[i]  = Wpro[i]; }
    if (tid < E_){ sbe[tid] = bemb[tid]; sbp[tid] = bpro[tid]; }
    __syncthreads();

    int warp = tid >> 5, lane = tid & 31;
    int r = blockIdx.x*8 + warp;
    int b = r >> 9; int n = (r >> 3) & 63; int d = r & 7;
    const float* xp = x + ((b*64 + n)*6)*8 + d;

    float v[6]; float s = 0.f;
    #pragma unroll
    for (int p = 0; p < 6; p++){ v[p] = xp[p*8]; s += v[p]; }
    float mean = s * (1.f/6.f);
    float var = 0.f;
    #pragma unroll
    for (int p = 0; p < 6; p++){ float dd = v[p]-mean; var += dd*dd; }
    var *= (1.f/6.f);
    float rs = rsqrtf(var + 1e-5f);
    float xn[6];
    #pragma unroll
    for (int p = 0; p < 6; p++) xn[p] = (v[p]-mean)*rs;

    float best = -1e30f; int bi = 0;
    #pragma unroll
    for (int i = 0; i < 8; i++){
        int pidx = i*32 + lane;
        const float* pr = &sPNL2[pidx*6];
        float sim = xn[0]*pr[0] + xn[1]*pr[1] + xn[2]*pr[2]
                  + xn[3]*pr[3] + xn[4]*pr[4] + xn[5]*pr[5];
        if (sim > best){ best = sim; bi = pidx; }
    }
    #pragma unroll
    for (int off = 16; off; off >>= 1){
        float ov = __shfl_xor_sync(0xffffffffu, best, off);
        int   oi = __shfl_xor_sync(0xffffffffu, bi,   off);
        if (ov > best || (ov == best && oi < bi)){ best = ov; bi = oi; }
    }

    float sel[6];
    #pragma unroll
    for (int p = 0; p < 6; p++) sel[p] = sPN[bi*6 + p];

    #pragma unroll
    for (int e4 = 0; e4 < 4; e4++){
        int e = e4*32 + lane;
        const float* we = &sWe[e*6];
        const float* wp = &sWp[e*6];
        float a1 = sbe[e], a2 = sbp[e];
        #pragma unroll
        for (int p = 0; p < 6; p++){ a1 += xn[p]*we[p]; a2 += sel[p]*wp[p]; }
        g_IE[r*E_ + e] = a1;
        g_PE[r*E_ + e] = a2;
    }
}

// ---------------- tf32 tensor-core GEMM: C[M,Nn] = A[M,K] @ W[Nn,K]^T + bias ----
// block = 256 threads (8 warps), block tile 128(M) x 64(N), warp tile 32x32.
// K staged through smem in 32-wide slabs, tf32-converted at stage time.
// CONCAT=1: A rows follow the per-batch [IE;PE] concat layout.
template<int RELU, int CONCAT, int KK>
__global__ void __launch_bounds__(256) k_mmagemm(int aId, const float* __restrict__ W,
                        const float* __restrict__ bias, int cId, int Nn){
    __shared__ unsigned sA[128*36];
    __shared__ unsigned sW[64*36];
    float* C = bufptr(cId);
    int t = threadIdx.x;
    int m0 = blockIdx.x * 128, n0 = blockIdx.y * 64;
    const float* Abase;
    if (CONCAT){
        int bb = m0 >> 10, j = m0 & 1023;
        Abase = ((j < 512) ? g_IE : g_PE) + (size_t)(bb*512 + (j & 511)) * KK;
    } else {
        Abase = bufptr(aId) + (size_t)m0 * KK;
    }
    int lane = t & 31, warp = t >> 5;
    int wm = warp >> 1, wn = warp & 1;
    int lq = lane >> 2, lc = lane & 3;

    float c[2][4][4];
    #pragma unroll
    for (int mt = 0; mt < 2; mt++)
        #pragma unroll
        for (int nt = 0; nt < 4; nt++)
            c[mt][nt][0]=c[mt][nt][1]=c[mt][nt][2]=c[mt][nt][3]=0.f;

    for (int k0 = 0; k0 < KK; k0 += 32){
        // stage A tile 128x32
        #pragma unroll
        for (int i = 0; i < 4; i++){
            int f = t + i*256;               // float4 id, 1024 total
            int row = f >> 3, c4 = (f & 7)*4;
            float4 v = *(const float4*)&Abase[(size_t)row*KK + k0 + c4];
            unsigned* dst = &sA[row*36 + c4];
            dst[0]=f2tf(v.x); dst[1]=f2tf(v.y); dst[2]=f2tf(v.z); dst[3]=f2tf(v.w);
        }
        // stage W tile 64x32
        #pragma unroll
        for (int i = 0; i < 2; i++){
            int f = t + i*256;               // 512 total
            int row = f >> 3, c4 = (f & 7)*4;
            float4 v = *(const float4*)&W[(size_t)(n0+row)*KK + k0 + c4];
            unsigned* dst = &sW[row*36 + c4];
            dst[0]=f2tf(v.x); dst[1]=f2tf(v.y); dst[2]=f2tf(v.z); dst[3]=f2tf(v.w);
        }
        __syncthreads();
        #pragma unroll
        for (int ks = 0; ks < 4; ks++){
            int k = ks*8;
            unsigned a[2][4], bf[4][2];
            #pragma unroll
            for (int mt = 0; mt < 2; mt++){
                int r = wm*32 + mt*16 + lq;
                a[mt][0] = sA[r*36 + k + lc];
                a[mt][1] = sA[(r+8)*36 + k + lc];
                a[mt][2] = sA[r*36 + k + lc + 4];
                a[mt][3] = sA[(r+8)*36 + k + lc + 4];
            }
            #pragma unroll
            for (int nt = 0; nt < 4; nt++){
                int n = wn*32 + nt*8 + lq;
                bf[nt][0] = sW[n*36 + k + lc];
                bf[nt][1] = sW[n*36 + k + lc + 4];
            }
            #pragma unroll
            for (int mt = 0; mt < 2; mt++)
                #pragma unroll
                for (int nt = 0; nt < 4; nt++)
                    mma_tf32(c[mt][nt], a[mt], bf[nt]);
        }
        __syncthreads();
    }
    // epilogue: bias (+relu), float2 stores
    #pragma unroll
    for (int nt = 0; nt < 4; nt++){
        int col = n0 + wn*32 + nt*8 + 2*lc;
        float b0 = bias[col], b1 = bias[col+1];
        #pragma unroll
        for (int mt = 0; mt < 2; mt++){
            int row = m0 + wm*32 + mt*16 + lq;
            float v0 = c[mt][nt][0] + b0, v1 = c[mt][nt][1] + b1;
            float v2 = c[mt][nt][2] + b0, v3 = c[mt][nt][3] + b1;
            if (RELU){
                v0 = fmaxf(v0,0.f); v1 = fmaxf(v1,0.f);
                v2 = fmaxf(v2,0.f); v3 = fmaxf(v3,0.f);
            }
            *(float2*)&C[(size_t)row*Nn + col]     = make_float2(v0, v1);
            *(float2*)&C[(size_t)(row+8)*Nn + col] = make_float2(v2, v3);
        }
    }
}

// ---------------- per (qrow, head) L2 norm of q ----------------
__global__ void k_qn(){
    int i = blockIdx.x*256 + threadIdx.x;      // 0..65535 = row*8+h
    int row = i >> 3, h = i & 7;
    const float4* q = (const float4*)(g_Q + (size_t)row*E_ + h*16);
    float4 a = q[0], b = q[1], c = q[2], d = q[3];
    float s = a.x*a.x+a.y*a.y+a.z*a.z+a.w*a.w
            + b.x*b.x+b.y*b.y+b.z*b.z+b.w*b.w
            + c.x*c.x+c.y*c.y+c.z*c.z+c.w*c.w
            + d.x*d.x+d.y*d.y+d.z*d.z+d.w*d.w;
    g_QN[i] = sqrtf(s);
}

// ---------------- per (b, head) max key L2 norm ----------------
__global__ void k_kmax(){
    int bh = blockIdx.x; int b = bh >> 3, h = bh & 7;
    const float* base = g_KVO + (size_t)(b*1024)*256 + h*16;
    float mx = 0.f;
    for (int j = threadIdx.x; j < 1024; j += 256){
        const float4* kp = (const float4*)(base + (size_t)j*256);
        float4 a = kp[0], bb = kp[1], c = kp[2], d = kp[3];
        float s = a.x*a.x+a.y*a.y+a.z*a.z+a.w*a.w
                + bb.x*bb.x+bb.y*bb.y+bb.z*bb.z+bb.w*bb.w
                + c.x*c.x+c.y*c.y+c.z*c.z+c.w*c.w
                + d.x*d.x+d.y*d.y+d.z*d.z+d.w*d.w;
        mx = fmaxf(mx, s);
    }
    #pragma unroll
    for (int off = 16; off; off >>= 1)
        mx = fmaxf(mx, __shfl_xor_sync(0xffffffffu, mx, off));
    __shared__ float red[8];
    if ((threadIdx.x & 31) == 0) red[threadIdx.x >> 5] = mx;
    __syncthreads();
    if (threadIdx.x == 0){
        float m = red[0];
        #pragma unroll
        for (int w = 1; w < 8; w++) m = fmaxf(m, red[w]);
        g_KMAX[bh] = sqrtf(m);
    }
}

// ---------------- attention with tf32 mma: bound-shifted single-pass softmax ----
__global__ void __launch_bounds__(128) k_attn(){
    int blk = blockIdx.x;                 // 0..255
    int bh = blk >> 1, qh = blk & 1;
    int b = bh >> 3, h = bh & 7;
    int lane = threadIdx.x & 31, warp = threadIdx.x >> 5;
    int lq = lane >> 2, lc = lane & 3;
    int qrow0 = b*512 + qh*256 + warp*64;
    int hoff = h*16;
    const float* Qb  = g_Q  + (size_t)qrow0*E_ + hoff;
    const float* KVb = g_KVO + (size_t)(b*1024)*256;

    unsigned qa[4][2][4];
    #pragma unroll
    for (int mt = 0; mt < 4; mt++)
        #pragma unroll
        for (int ks = 0; ks < 2; ks++){
            const float* qp = Qb + (size_t)(mt*16)*E_ + ks*8;
            qa[mt][ks][0] = f2tf(qp[(size_t)lq*E_     + lc]);
            qa[mt][ks][1] = f2tf(qp[(size_t)(lq+8)*E_ + lc]);
            qa[mt][ks][2] = f2tf(qp[(size_t)lq*E_     + lc+4]);
            qa[mt][ks][3] = f2tf(qp[(size_t)(lq+8)*E_ + lc+4]);
        }

    float kmax = g_KMAX[bh];
    float mb[4][2];
    #pragma unroll
    for (int mt = 0; mt < 4; mt++){
        mb[mt][0] = g_QN[(qrow0 + mt*16 + lq  )*8 + h] * kmax * 0.25f;
        mb[mt][1] = g_QN[(qrow0 + mt*16 + lq+8)*8 + h] * kmax * 0.25f;
    }

    float o[4][2][4];
    #pragma unroll
    for (int mt = 0; mt < 4; mt++)
        #pragma unroll
        for (int d = 0; d < 2; d++)
            o[mt][d][0]=o[mt][d][1]=o[mt][d][2]=o[mt][d][3]=0.f;
    float lsum[4][2] = {};

    int s1 = (lane & 28) | (lc >> 1);
    int s2 = s1 + 2;
    bool odd = lc & 1;

    #pragma unroll 1
    for (int key0 = 0; key0 < 1024; key0 += 16){
        unsigned kb[2][2][2];
        const float* kbase = KVb + (size_t)key0*256 + hoff;
        #pragma unroll
        for (int nt = 0; nt < 2; nt++)
            #pragma unroll
            for (int ks = 0; ks < 2; ks++){
                const float* kp = kbase + (size_t)(nt*8 + lq)*256 + ks*8 + lc;
                kb[nt][ks][0] = f2tf(kp[0]);
                kb[nt][ks][1] = f2tf(kp[4]);
            }
        float s[4][2][4];
        #pragma unroll
        for (int mt = 0; mt < 4; mt++)
            #pragma unroll
            for (int nt = 0; nt < 2; nt++){
                s[mt][nt][0]=s[mt][nt][1]=s[mt][nt][2]=s[mt][nt][3]=0.f;
                mma_tf32(s[mt][nt], qa[mt][0], kb[nt][0]);
                mma_tf32(s[mt][nt], qa[mt][1], kb[nt][1]);
            }
        #pragma unroll
        for (int mt = 0; mt < 4; mt++)
            #pragma unroll
            for (int nt = 0; nt < 2; nt++){
                float p0 = __expf(s[mt][nt][0]*0.25f - mb[mt][0]);
                float p1 = __expf(s[mt][nt][1]*0.25f - mb[mt][0]);
                float p2 = __expf(s[mt][nt][2]*0.25f - mb[mt][1]);
                float p3 = __expf(s[mt][nt][3]*0.25f - mb[mt][1]);
                float q0 = __uint_as_float(f2tf(p0));
                float q1 = __uint_as_float(f2tf(p1));
                float q2 = __uint_as_float(f2tf(p2));
                float q3 = __uint_as_float(f2tf(p3));
                s[mt][nt][0]=q0; s[mt][nt][1]=q1; s[mt][nt][2]=q2; s[mt][nt][3]=q3;
                lsum[mt][0] += q0 + q1;
                lsum[mt][1] += q2 + q3;
            }
        unsigned vb[2][2][2];
        const float* vbase = KVb + (size_t)key0*256 + 128 + hoff;
        #pragma unroll
        for (int kt = 0; kt < 2; kt++)
            #pragma unroll
            for (int d = 0; d < 2; d++){
                const float* vp = vbase + (size_t)(kt*8 + lc)*256 + d*8 + lq;
                vb[kt][d][0] = f2tf(vp[0]);
                vb[kt][d][1] = f2tf(vp[4*256]);
            }
        #pragma unroll
        for (int mt = 0; mt < 4; mt++)
            #pragma unroll
            for (int kt = 0; kt < 2; kt++){
                unsigned a[4];
                float w0 = __shfl_sync(0xffffffffu, s[mt][kt][0], s1);
                float w1 = __shfl_sync(0xffffffffu, s[mt][kt][1], s1);
                a[0] = __float_as_uint(odd ? w1 : w0);
                float w2 = __shfl_sync(0xffffffffu, s[mt][kt][2], s1);
                float w3 = __shfl_sync(0xffffffffu, s[mt][kt][3], s1);
                a[1] = __float_as_uint(odd ? w3 : w2);
                w0 = __shfl_sync(0xffffffffu, s[mt][kt][0], s2);
                w1 = __shfl_sync(0xffffffffu, s[mt][kt][1], s2);
                a[2] = __float_as_uint(odd ? w1 : w0);
                w2 = __shfl_sync(0xffffffffu, s[mt][kt][2], s2);
                w3 = __shfl_sync(0xffffffffu, s[mt][kt][3], s2);
                a[3] = __float_as_uint(odd ? w3 : w2);
                mma_tf32(o[mt][0], a, vb[kt][0]);
                mma_tf32(o[mt][1], a, vb[kt][1]);
            }
    }

    float inv[4][2];
    #pragma unroll
    for (int mt = 0; mt < 4; mt++)
        #pragma unroll
        for (int hf = 0; hf < 2; hf++){
            float l = lsum[mt][hf];
            l += __shfl_xor_sync(0xffffffffu, l, 1);
            l += __shfl_xor_sync(0xffffffffu, l, 2);
            inv[mt][hf] = 1.f / l;
        }
    #pragma unroll
    for (int mt = 0; mt < 4; mt++)
        #pragma unroll
        for (int d = 0; d < 2; d++){
            float* op = g_AT + (size_t)(qrow0 + mt*16 + lq)*E_ + hoff + d*8 + 2*lc;
            *(float2*)op = make_float2(o[mt][d][0]*inv[mt][0], o[mt][d][1]*inv[mt][0]);
            *(float2*)(op + 8*E_) = make_float2(o[mt][d][2]*inv[mt][1], o[mt][d][3]*inv[mt][1]);
        }
}

// ---------------- residual + LayerNorm (row = 128) ----------------
__global__ void k_lnres(int aId, int rId, const float* __restrict__ g,
                        const float* __restrict__ be, int oId){
    const float* A = bufptr(aId);
    const float* R = bufptr(rId);
    float* out = bufptr(oId);
    int tid = threadIdx.x; int warp = tid >> 5, lane = tid & 31;
    int row = blockIdx.x*8 + warp;
    float v[4];
    #pragma unroll
    for (int i = 0; i < 4; i++){
        int e = i*32 + lane;
        v[i] = A[(size_t)row*E_ + e] + R[(size_t)row*E_ + e];
    }
    float s  = v[0]+v[1]+v[2]+v[3];
    float s2 = v[0]*v[0]+v[1]*v[1]+v[2]*v[2]+v[3]*v[3];
    #pragma unroll
    for (int off = 16; off; off >>= 1){
        s  += __shfl_xor_sync(0xffffffffu, s,  off);
        s2 += __shfl_xor_sync(0xffffffffu, s2, off);
    }
    float mean = s * (1.f/128.f);
    float var  = s2 * (1.f/128.f) - mean*mean;
    float rs = rsqrtf(var + 1e-5f);
    #pragma unroll
    for (int i = 0; i < 4; i++){
        int e = i*32 + lane;
        out[(size_t)row*E_ + e] = (v[i]-mean)*rs*g[e] + be[e];
    }
}

// ---------------- final projection: split-K over 65536 (fp32 for accuracy) ----
__global__ void k_splitk(const float* __restrict__ W){
    __shared__ float Zs[16*32];
    __shared__ float Ws_[32*129];
    int t = threadIdx.x;
    int kb = blockIdx.x * KCSZ_;
    int o = t & 127;
    int bset = t >> 7;
    float acc[8];
    #pragma unroll
    for (int i = 0; i < 8; i++) acc[i] = 0.f;
    for (int k0 = 0; k0 < KCSZ_; k0 += 32){
        #pragma unroll
        for (int i = 0; i < 2; i++){
            int e = t + i*256; int b_ = e >> 5, kk = e & 31;
            Zs[b_*32 + kk] = g_Z[(size_t)b_*KOUT_ + kb + k0 + kk];
        }
        #pragma unroll
        for (int i = 0; i < 16; i++){
            int e = t + i*256; int oo = e >> 5, kk = e & 31;
            Ws_[kk*129 + oo] = W[(size_t)oo*KOUT_ + kb + k0 + kk];
        }
        __syncthreads();
        #pragma unroll
        for (int kk = 0; kk < 32; kk++){
            float w = Ws_[kk*129 + o];
            #pragma unroll
            for (int i = 0; i < 8; i++)
                acc[i] += Zs[(bset*8 + i)*32 + kk] * w;
        }
        __syncthreads();
    }
    #pragma unroll
    for (int i = 0; i < 8; i++)
        g_PART[blockIdx.x*2048 + (bset*8 + i)*128 + o] = acc[i];
}

__global__ void k_reduce(const float* __restrict__ bout, float* __restrict__ out){
    int e = blockIdx.x*256 + threadIdx.x;   // 0..2047
    float s = bout[e & 127];
    #pragma unroll 8
    for (int c = 0; c < KCHUNKS_; c++) s += g_PART[c*2048 + e];
    out[e] = s;
}

// ---------------- launch ----------------
extern "C" void kernel_launch(void* const* d_in, const int* in_sizes, int n_in,
                              void* d_out, int out_size){
    const float* x    = (const float*)d_in[0];
    const float* prot = (const float*)d_in[1];
    const float* Wemb = (const float*)d_in[2];
    const float* bemb = (const float*)d_in[3];
    const float* Wpro = (const float*)d_in[4];
    const float* bpro = (const float*)d_in[5];
    const float* inw  = (const float*)d_in[6];
    const float* inb  = (const float*)d_in[7];
    const float* ow   = (const float*)d_in[8];
    const float* ob   = (const float*)d_in[9];
    const float* W1   = (const float*)d_in[10];
    const float* b1   = (const float*)d_in[11];
    const float* W2   = (const float*)d_in[12];
    const float* b2   = (const float*)d_in[13];
    const float* g1   = (const float*)d_in[14];
    const float* be1  = (const float*)d_in[15];
    const float* g2   = (const float*)d_in[16];
    const float* be2  = (const float*)d_in[17];
    const float* Wout = (const float*)d_in[18];
    const float* bout = (const float*)d_in[19];
    float* out = (float*)d_out;

    // 1. prototype norms
    k_proto<<<1, 256>>>(prot);
    // 2. inorm + argmax + embeddings
    k_rowprep<<<1024, 256>>>(x, Wemb, bemb, Wpro, bpro);
    // 3. Q projection: IE(0) -> Q(2)   [tf32 mma]
    k_mmagemm<0,0,128><<<dim3(TOK_/128, 2), 256>>>(0, inw, inb, 2, 128);
    // 4. fused K|V projection with virtual [IE;PE] concat -> KVO(3)  [tf32 mma]
    k_mmagemm<0,1,128><<<dim3(KVN_/128, 4), 256>>>(0, inw + 128*E_, inb + 128, 3, 256);
    // 5. softmax bound prep
    k_qn<<<TOK_*H_/256, 256>>>();
    k_kmax<<<B_*H_, 256>>>();
    // 6. attention (tf32 tensor cores)
    k_attn<<<B_*H_*2, 128>>>();
    // 7. out_proj: AT(4) -> AP(5)  [tf32 mma]
    k_mmagemm<0,0,128><<<dim3(TOK_/128, 2), 256>>>(4, ow, ob, 5, 128);
    // 8. h1 = LN(IE + AP)
    k_lnres<<<TOK_/8, 256>>>(0, 5, g1, be1, 6);
    // 9. ffn1 = relu(h1 @ W1^T + b1): H1(6) -> F1(7)  [tf32 mma]
    k_mmagemm<1,0,128><<<dim3(TOK_/128, 1), 256>>>(6, W1, b1, 7, 64);
    // 10. ffn2: F1(7) -> F2(8)  [tf32 mma, K=64]
    k_mmagemm<0,0,64><<<dim3(TOK_/128, 2), 256>>>(7, W2, b2, 8, 128);
    // 11. z = LN(h1 + ffn2)
    k_lnres<<<TOK_/8, 256>>>(6, 8, g2, be2, 9);
    // 12. final projection split-K + reduce (fp32)
    k_splitk<<<KCHUNKS_, 256>>>(Wout);
    k_reduce<<<8, 256>>>(bout, out);
}

// round 8
// speedup vs baseline: 1.5585x; 1.0172x over previous
#include <cuda_runtime.h>

// ---------------- problem constants ----------------
#define B_      16
#define N_      64
#define P_      6
#define D_      8
#define E_      128
#define H_      8
#define HD_     16
#define S_      512            // N*D tokens per batch
#define TOK_    (B_*S_)        // 8192
#define KVN_    (B_*2*S_)      // 16384
#define NPROTO_ 256            // D * 32 prototype rows
#define I_      64
#define O_      128
#define KOUT_   (S_*E_)        // 65536
#define KCHUNKS_ 128
#define KCSZ_   (KOUT_/KCHUNKS_) // 512

// ---------------- device scratch (no allocations allowed) ----------------
__device__ float g_PN  [NPROTO_*P_];
__device__ float g_PNL2[NPROTO_*P_];
__device__ float g_IE  [TOK_*E_];
__device__ float g_PE  [TOK_*E_];
__device__ float g_Q   [TOK_*E_];
__device__ float g_KVO [KVN_*2*E_];   // cols 0..127 = K, 128..255 = V
__device__ float g_AT  [TOK_*E_];
__device__ float g_AP  [TOK_*E_];
__device__ float g_H1  [TOK_*E_];
__device__ float g_F1  [TOK_*I_];
__device__ float g_F2  [TOK_*E_];
__device__ float g_Z   [TOK_*E_];
__device__ float g_PART[KCHUNKS_*B_*O_];
__device__ float g_QN  [TOK_*H_];     // per (qrow, head) L2 norm
__device__ float g_KMAX[B_*H_];       // per (b, head) max key L2 norm

__device__ __forceinline__ float* bufptr(int id){
    switch(id){
        case 0: return g_IE;
        case 2: return g_Q;
        case 3: return g_KVO;
        case 4: return g_AT;
        case 5: return g_AP;
        case 6: return g_H1;
        case 7: return g_F1;
        case 8: return g_F2;
        default: return g_Z;
    }
}

// ---------------- tf32 helpers ----------------
__device__ __forceinline__ unsigned f2tf(float f){
    unsigned r; asm("cvt.rna.tf32.f32 %0, %1;" : "=r"(r) : "f"(f)); return r;
}
__device__ __forceinline__ void mma_tf32(float c[4], const unsigned a[4], const unsigned b[2]){
    asm volatile("mma.sync.aligned.m16n8k8.row.col.f32.tf32.tf32.f32 "
        "{%0,%1,%2,%3}, {%4,%5,%6,%7}, {%8,%9}, {%0,%1,%2,%3};"
        : "+f"(c[0]), "+f"(c[1]), "+f"(c[2]), "+f"(c[3])
        : "r"(a[0]), "r"(a[1]), "r"(a[2]), "r"(a[3]), "r"(b[0]), "r"(b[1]));
}

// ---------------- prototype instance-norm + L2 ----------------
__global__ void k_proto(const float* __restrict__ proto){
    int t = threadIdx.x;
    if (t >= NPROTO_) return;
    float v[P_]; float s = 0.f;
    #pragma unroll
    for (int p = 0; p < P_; p++){ v[p] = proto[t*P_ + p]; s += v[p]; }
    float m = s * (1.f/P_);
    float var = 0.f;
    #pragma unroll
    for (int p = 0; p < P_; p++){ float d = v[p]-m; var += d*d; }
    var *= (1.f/P_);
    float rs = rsqrtf(var + 1e-5f);
    float nrm = 0.f;
    #pragma unroll
    for (int p = 0; p < P_; p++){ v[p] = (v[p]-m)*rs; nrm += v[p]*v[p]; g_PN[t*P_+p] = v[p]; }
    float inv = 1.f / fmaxf(sqrtf(nrm), 1e-12f);
    #pragma unroll
    for (int p = 0; p < P_; p++) g_PNL2[t*P_+p] = v[p]*inv;
}

// ---------------- per-row inorm + argmax lookup + both embeddings ----------------
__global__ void k_rowprep(const float* __restrict__ x,
                          const float* __restrict__ Wemb, const float* __restrict__ bemb,
                          const float* __restrict__ Wpro, const float* __restrict__ bpro){
    __shared__ float sPN  [NPROTO_*P_];
    __shared__ float sPNL2[NPROTO_*P_];
    __shared__ float sWe[E_*P_];
    __shared__ float sWp[E_*P_];
    __shared__ float sbe[E_];
    __shared__ float sbp[E_];
    int tid = threadIdx.x;
    for (int i = tid; i < NPROTO_*P_; i += 256){ sPN[i] = g_PN[i]; sPNL2[i] = g_PNL2[i]; }
    for (int i = tid; i < E_*P_;     i += 256){ sWe[i] = Wemb[i];  sWp[i]  = Wpro[i]; }
    if (tid < E_){ sbe[tid] = bemb[tid]; sbp[tid] = bpro[tid]; }
    __syncthreads();

    int warp = tid >> 5, lane = tid & 31;
    int r = blockIdx.x*8 + warp;
    int b = r >> 9; int n = (r >> 3) & 63; int d = r & 7;
    const float* xp = x + ((b*64 + n)*6)*8 + d;

    float v[6]; float s = 0.f;
    #pragma unroll
    for (int p = 0; p < 6; p++){ v[p] = xp[p*8]; s += v[p]; }
    float mean = s * (1.f/6.f);
    float var = 0.f;
    #pragma unroll
    for (int p = 0; p < 6; p++){ float dd = v[p]-mean; var += dd*dd; }
    var *= (1.f/6.f);
    float rs = rsqrtf(var + 1e-5f);
    float xn[6];
    #pragma unroll
    for (int p = 0; p < 6; p++) xn[p] = (v[p]-mean)*rs;

    float best = -1e30f; int bi = 0;
    #pragma unroll
    for (int i = 0; i < 8; i++){
        int pidx = i*32 + lane;
        const float* pr = &sPNL2[pidx*6];
        float sim = xn[0]*pr[0] + xn[1]*pr[1] + xn[2]*pr[2]
                  + xn[3]*pr[3] + xn[4]*pr[4] + xn[5]*pr[5];
        if (sim > best){ best = sim; bi = pidx; }
    }
    #pragma unroll
    for (int off = 16; off; off >>= 1){
        float ov = __shfl_xor_sync(0xffffffffu, best, off);
        int   oi = __shfl_xor_sync(0xffffffffu, bi,   off);
        if (ov > best || (ov == best && oi < bi)){ best = ov; bi = oi; }
    }

    float sel[6];
    #pragma unroll
    for (int p = 0; p < 6; p++) sel[p] = sPN[bi*6 + p];

    #pragma unroll
    for (int e4 = 0; e4 < 4; e4++){
        int e = e4*32 + lane;
        const float* we = &sWe[e*6];
        const float* wp = &sWp[e*6];
        float a1 = sbe[e], a2 = sbp[e];
        #pragma unroll
        for (int p = 0; p < 6; p++){ a1 += xn[p]*we[p]; a2 += sel[p]*wp[p]; }
        g_IE[r*E_ + e] = a1;
        g_PE[r*E_ + e] = a2;
    }
}

// ---------------- tf32 tensor-core GEMM: C[M,Nn] = A[M,K] @ W[Nn,K]^T + bias ----
// block = 256 threads (8 warps), block tile 128(M) x 64(N), warp tile 32x32.
// Register-prefetch pipeline over 32-wide K slabs.
// CONCAT=1: A rows follow the per-batch [IE;PE] concat layout.
template<int RELU, int CONCAT, int KK>
__global__ void __launch_bounds__(256) k_mmagemm(int aId, const float* __restrict__ W,
                        const float* __restrict__ bias, int cId, int Nn){
    __shared__ unsigned sA[128*36];
    __shared__ unsigned sW[64*36];
    float* C = bufptr(cId);
    int t = threadIdx.x;
    int m0 = blockIdx.x * 128, n0 = blockIdx.y * 64;
    const float* Abase;
    if (CONCAT){
        int bb = m0 >> 10, j = m0 & 1023;
        Abase = ((j < 512) ? g_IE : g_PE) + (size_t)(bb*512 + (j & 511)) * KK;
    } else {
        Abase = bufptr(aId) + (size_t)m0 * KK;
    }
    int lane = t & 31, warp = t >> 5;
    int wm = warp >> 1, wn = warp & 1;
    int lq = lane >> 2, lc = lane & 3;
    int arow = t >> 3, ac4 = (t & 7)*4;

    float c[2][4][4];
    #pragma unroll
    for (int mt = 0; mt < 2; mt++)
        #pragma unroll
        for (int nt = 0; nt < 4; nt++)
            c[mt][nt][0]=c[mt][nt][1]=c[mt][nt][2]=c[mt][nt][3]=0.f;

    // prefetch first slab
    float4 pa[4], pw[2];
    #pragma unroll
    for (int i = 0; i < 4; i++)
        pa[i] = *(const float4*)&Abase[(size_t)(arow + i*32)*KK + ac4];
    #pragma unroll
    for (int i = 0; i < 2; i++)
        pw[i] = *(const float4*)&W[(size_t)(n0 + arow + i*32)*KK + ac4];

    for (int k0 = 0; k0 < KK; k0 += 32){
        #pragma unroll
        for (int i = 0; i < 4; i++){
            unsigned* d = &sA[(arow + i*32)*36 + ac4];
            d[0]=f2tf(pa[i].x); d[1]=f2tf(pa[i].y); d[2]=f2tf(pa[i].z); d[3]=f2tf(pa[i].w);
        }
        #pragma unroll
        for (int i = 0; i < 2; i++){
            unsigned* d = &sW[(arow + i*32)*36 + ac4];
            d[0]=f2tf(pw[i].x); d[1]=f2tf(pw[i].y); d[2]=f2tf(pw[i].z); d[3]=f2tf(pw[i].w);
        }
        __syncthreads();
        if (k0 + 32 < KK){
            #pragma unroll
            for (int i = 0; i < 4; i++)
                pa[i] = *(const float4*)&Abase[(size_t)(arow + i*32)*KK + k0 + 32 + ac4];
            #pragma unroll
            for (int i = 0; i < 2; i++)
                pw[i] = *(const float4*)&W[(size_t)(n0 + arow + i*32)*KK + k0 + 32 + ac4];
        }
        #pragma unroll
        for (int ks = 0; ks < 4; ks++){
            int k = ks*8;
            unsigned a[2][4], bf[4][2];
            #pragma unroll
            for (int mt = 0; mt < 2; mt++){
                int r = wm*32 + mt*16 + lq;
                a[mt][0] = sA[r*36 + k + lc];
                a[mt][1] = sA[(r+8)*36 + k + lc];
                a[mt][2] = sA[r*36 + k + lc + 4];
                a[mt][3] = sA[(r+8)*36 + k + lc + 4];
            }
            #pragma unroll
            for (int nt = 0; nt < 4; nt++){
                int n = wn*32 + nt*8 + lq;
                bf[nt][0] = sW[n*36 + k + lc];
                bf[nt][1] = sW[n*36 + k + lc + 4];
            }
            #pragma unroll
            for (int mt = 0; mt < 2; mt++)
                #pragma unroll
                for (int nt = 0; nt < 4; nt++)
                    mma_tf32(c[mt][nt], a[mt], bf[nt]);
        }
        __syncthreads();
    }
    // epilogue: bias (+relu), float2 stores
    #pragma unroll
    for (int nt = 0; nt < 4; nt++){
        int col = n0 + wn*32 + nt*8 + 2*lc;
        float b0 = bias[col], b1 = bias[col+1];
        #pragma unroll
        for (int mt = 0; mt < 2; mt++){
            int row = m0 + wm*32 + mt*16 + lq;
            float v0 = c[mt][nt][0] + b0, v1 = c[mt][nt][1] + b1;
            float v2 = c[mt][nt][2] + b0, v3 = c[mt][nt][3] + b1;
            if (RELU){
                v0 = fmaxf(v0,0.f); v1 = fmaxf(v1,0.f);
                v2 = fmaxf(v2,0.f); v3 = fmaxf(v3,0.f);
            }
            *(float2*)&C[(size_t)row*Nn + col]     = make_float2(v0, v1);
            *(float2*)&C[(size_t)(row+8)*Nn + col] = make_float2(v2, v3);
        }
    }
}

// ---------------- per (qrow, head) L2 norm of q ----------------
__global__ void k_qn(){
    int i = blockIdx.x*256 + threadIdx.x;      // 0..65535 = row*8+h
    int row = i >> 3, h = i & 7;
    const float4* q = (const float4*)(g_Q + (size_t)row*E_ + h*16);
    float4 a = q[0], b = q[1], c = q[2], d = q[3];
    float s = a.x*a.x+a.y*a.y+a.z*a.z+a.w*a.w
            + b.x*b.x+b.y*b.y+b.z*b.z+b.w*b.w
            + c.x*c.x+c.y*c.y+c.z*c.z+c.w*c.w
            + d.x*d.x+d.y*d.y+d.z*d.z+d.w*d.w;
    g_QN[i] = sqrtf(s);
}

// ---------------- per (b, head) max key L2 norm ----------------
__global__ void k_kmax(){
    int bh = blockIdx.x; int b = bh >> 3, h = bh & 7;
    const float* base = g_KVO + (size_t)(b*1024)*256 + h*16;
    float mx = 0.f;
    for (int j = threadIdx.x; j < 1024; j += 256){
        const float4* kp = (const float4*)(base + (size_t)j*256);
        float4 a = kp[0], bb = kp[1], c = kp[2], d = kp[3];
        float s = a.x*a.x+a.y*a.y+a.z*a.z+a.w*a.w
                + bb.x*bb.x+bb.y*bb.y+bb.z*bb.z+bb.w*bb.w
                + c.x*c.x+c.y*c.y+c.z*c.z+c.w*c.w
                + d.x*d.x+d.y*d.y+d.z*d.z+d.w*d.w;
        mx = fmaxf(mx, s);
    }
    #pragma unroll
    for (int off = 16; off; off >>= 1)
        mx = fmaxf(mx, __shfl_xor_sync(0xffffffffu, mx, off));
    __shared__ float red[8];
    if ((threadIdx.x & 31) == 0) red[threadIdx.x >> 5] = mx;
    __syncthreads();
    if (threadIdx.x == 0){
        float m = red[0];
        #pragma unroll
        for (int w = 1; w < 8; w++) m = fmaxf(m, red[w]);
        g_KMAX[bh] = sqrtf(m);
    }
}

// ---------------- attention with tf32 mma: bound-shifted single-pass softmax ----
__global__ void __launch_bounds__(128) k_attn(){
    int blk = blockIdx.x;                 // 0..255
    int bh = blk >> 1, qh = blk & 1;
    int b = bh >> 3, h = bh & 7;
    int lane = threadIdx.x & 31, warp = threadIdx.x >> 5;
    int lq = lane >> 2, lc = lane & 3;
    int qrow0 = b*512 + qh*256 + warp*64;
    int hoff = h*16;
    const float* Qb  = g_Q  + (size_t)qrow0*E_ + hoff;
    const float* KVb = g_KVO + (size_t)(b*1024)*256;

    unsigned qa[4][2][4];
    #pragma unroll
    for (int mt = 0; mt < 4; mt++)
        #pragma unroll
        for (int ks = 0; ks < 2; ks++){
            const float* qp = Qb + (size_t)(mt*16)*E_ + ks*8;
            qa[mt][ks][0] = f2tf(qp[(size_t)lq*E_     + lc]);
            qa[mt][ks][1] = f2tf(qp[(size_t)(lq+8)*E_ + lc]);
            qa[mt][ks][2] = f2tf(qp[(size_t)lq*E_     + lc+4]);
            qa[mt][ks][3] = f2tf(qp[(size_t)(lq+8)*E_ + lc+4]);
        }

    float kmax = g_KMAX[bh];
    float mb[4][2];
    #pragma unroll
    for (int mt = 0; mt < 4; mt++){
        mb[mt][0] = g_QN[(qrow0 + mt*16 + lq  )*8 + h] * kmax * 0.25f;
        mb[mt][1] = g_QN[(qrow0 + mt*16 + lq+8)*8 + h] * kmax * 0.25f;
    }

    float o[4][2][4];
    #pragma unroll
    for (int mt = 0; mt < 4; mt++)
        #pragma unroll
        for (int d = 0; d < 2; d++)
            o[mt][d][0]=o[mt][d][1]=o[mt][d][2]=o[mt][d][3]=0.f;
    float lsum[4][2] = {};

    int s1 = (lane & 28) | (lc >> 1);
    int s2 = s1 + 2;
    bool odd = lc & 1;

    #pragma unroll 1
    for (int key0 = 0; key0 < 1024; key0 += 16){
        unsigned kb[2][2][2];
        const float* kbase = KVb + (size_t)key0*256 + hoff;
        #pragma unroll
        for (int nt = 0; nt < 2; nt++)
            #pragma unroll
            for (int ks = 0; ks < 2; ks++){
                const float* kp = kbase + (size_t)(nt*8 + lq)*256 + ks*8 + lc;
                kb[nt][ks][0] = f2tf(kp[0]);
                kb[nt][ks][1] = f2tf(kp[4]);
            }
        float s[4][2][4];
        #pragma unroll
        for (int mt = 0; mt < 4; mt++)
            #pragma unroll
            for (int nt = 0; nt < 2; nt++){
                s[mt][nt][0]=s[mt][nt][1]=s[mt][nt][2]=s[mt][nt][3]=0.f;
                mma_tf32(s[mt][nt], qa[mt][0], kb[nt][0]);
                mma_tf32(s[mt][nt], qa[mt][1], kb[nt][1]);
            }
        #pragma unroll
        for (int mt = 0; mt < 4; mt++)
            #pragma unroll
            for (int nt = 0; nt < 2; nt++){
                float p0 = __expf(s[mt][nt][0]*0.25f - mb[mt][0]);
                float p1 = __expf(s[mt][nt][1]*0.25f - mb[mt][0]);
                float p2 = __expf(s[mt][nt][2]*0.25f - mb[mt][1]);
                float p3 = __expf(s[mt][nt][3]*0.25f - mb[mt][1]);
                float q0 = __uint_as_float(f2tf(p0));
                float q1 = __uint_as_float(f2tf(p1));
                float q2 = __uint_as_float(f2tf(p2));
                float q3 = __uint_as_float(f2tf(p3));
                s[mt][nt][0]=q0; s[mt][nt][1]=q1; s[mt][nt][2]=q2; s[mt][nt][3]=q3;
                lsum[mt][0] += q0 + q1;
                lsum[mt][1] += q2 + q3;
            }
        unsigned vb[2][2][2];
        const float* vbase = KVb + (size_t)key0*256 + 128 + hoff;
        #pragma unroll
        for (int kt = 0; kt < 2; kt++)
            #pragma unroll
            for (int d = 0; d < 2; d++){
                const float* vp = vbase + (size_t)(kt*8 + lc)*256 + d*8 + lq;
                vb[kt][d][0] = f2tf(vp[0]);
                vb[kt][d][1] = f2tf(vp[4*256]);
            }
        #pragma unroll
        for (int mt = 0; mt < 4; mt++)
            #pragma unroll
            for (int kt = 0; kt < 2; kt++){
                unsigned a[4];
                float w0 = __shfl_sync(0xffffffffu, s[mt][kt][0], s1);
                float w1 = __shfl_sync(0xffffffffu, s[mt][kt][1], s1);
                a[0] = __float_as_uint(odd ? w1 : w0);
                float w2 = __shfl_sync(0xffffffffu, s[mt][kt][2], s1);
                float w3 = __shfl_sync(0xffffffffu, s[mt][kt][3], s1);
                a[1] = __float_as_uint(odd ? w3 : w2);
                w0 = __shfl_sync(0xffffffffu, s[mt][kt][0], s2);
                w1 = __shfl_sync(0xffffffffu, s[mt][kt][1], s2);
                a[2] = __float_as_uint(odd ? w1 : w0);
                w2 = __shfl_sync(0xffffffffu, s[mt][kt][2], s2);
                w3 = __shfl_sync(0xffffffffu, s[mt][kt][3], s2);
                a[3] = __float_as_uint(odd ? w3 : w2);
                mma_tf32(o[mt][0], a, vb[kt][0]);
                mma_tf32(o[mt][1], a, vb[kt][1]);
            }
    }

    float inv[4][2];
    #pragma unroll
    for (int mt = 0; mt < 4; mt++)
        #pragma unroll
        for (int hf = 0; hf < 2; hf++){
            float l = lsum[mt][hf];
            l += __shfl_xor_sync(0xffffffffu, l, 1);
            l += __shfl_xor_sync(0xffffffffu, l, 2);
            inv[mt][hf] = 1.f / l;
        }
    #pragma unroll
    for (int mt = 0; mt < 4; mt++)
        #pragma unroll
        for (int d = 0; d < 2; d++){
            float* op = g_AT + (size_t)(qrow0 + mt*16 + lq)*E_ + hoff + d*8 + 2*lc;
            *(float2*)op = make_float2(o[mt][d][0]*inv[mt][0], o[mt][d][1]*inv[mt][0]);
            *(float2*)(op + 8*E_) = make_float2(o[mt][d][2]*inv[mt][1], o[mt][d][3]*inv[mt][1]);
        }
}

// ---------------- residual + LayerNorm (row = 128) ----------------
__global__ void k_lnres(int aId, int rId, const float* __restrict__ g,
                        const float* __restrict__ be, int oId){
    const float* A = bufptr(aId);
    const float* R = bufptr(rId);
    float* out = bufptr(oId);
    int tid = threadIdx.x; int warp = tid >> 5, lane = tid & 31;
    int row = blockIdx.x*8 + warp;
    float v[4];
    #pragma unroll
    for (int i = 0; i < 4; i++){
        int e = i*32 + lane;
        v[i] = A[(size_t)row*E_ + e] + R[(size_t)row*E_ + e];
    }
    float s  = v[0]+v[1]+v[2]+v[3];
    float s2 = v[0]*v[0]+v[1]*v[1]+v[2]*v[2]+v[3]*v[3];
    #pragma unroll
    for (int off = 16; off; off >>= 1){
        s  += __shfl_xor_sync(0xffffffffu, s,  off);
        s2 += __shfl_xor_sync(0xffffffffu, s2, off);
    }
    float mean = s * (1.f/128.f);
    float var  = s2 * (1.f/128.f) - mean*mean;
    float rs = rsqrtf(var + 1e-5f);
    #pragma unroll
    for (int i = 0; i < 4; i++){
        int e = i*32 + lane;
        out[(size_t)row*E_ + e] = (v[i]-mean)*rs*g[e] + be[e];
    }
}

// ---------------- final projection: split-K over 65536 (fp32 for accuracy) ----
__global__ void k_splitk(const float* __restrict__ W){
    __shared__ float Zs[16*32];
    __shared__ float Ws_[32*129];
    int t = threadIdx.x;
    int kb = blockIdx.x * KCSZ_;
    int o = t & 127;
    int bset = t >> 7;
    float acc[8];
    #pragma unroll
    for (int i = 0; i < 8; i++) acc[i] = 0.f;
    for (int k0 = 0; k0 < KCSZ_; k0 += 32){
        #pragma unroll
        for (int i = 0; i < 2; i++){
            int e = t + i*256; int b_ = e >> 5, kk = e & 31;
            Zs[b_*32 + kk] = g_Z[(size_t)b_*KOUT_ + kb + k0 + kk];
        }
        #pragma unroll
        for (int i = 0; i < 16; i++){
            int e = t + i*256; int oo = e >> 5, kk = e & 31;
            Ws_[kk*129 + oo] = W[(size_t)oo*KOUT_ + kb + k0 + kk];
        }
        __syncthreads();
        #pragma unroll
        for (int kk = 0; kk < 32; kk++){
            float w = Ws_[kk*129 + o];
            #pragma unroll
            for (int i = 0; i < 8; i++)
                acc[i] += Zs[(bset*8 + i)*32 + kk] * w;
        }
        __syncthreads();
    }
    #pragma unroll
    for (int i = 0; i < 8; i++)
        g_PART[blockIdx.x*2048 + (bset*8 + i)*128 + o] = acc[i];
}

__global__ void k_reduce(const float* __restrict__ bout, float* __restrict__ out){
    int e = blockIdx.x*256 + threadIdx.x;   // 0..2047
    float s = bout[e & 127];
    #pragma unroll 8
    for (int c = 0; c < KCHUNKS_; c++) s += g_PART[c*2048 + e];
    out[e] = s;
}

// ---------------- launch ----------------
extern "C" void kernel_launch(void* const* d_in, const int* in_sizes, int n_in,
                              void* d_out, int out_size){
    const float* x    = (const float*)d_in[0];
    const float* prot = (const float*)d_in[1];
    const float* Wemb = (const float*)d_in[2];
    const float* bemb = (const float*)d_in[3];
    const float* Wpro = (const float*)d_in[4];
    const float* bpro = (const float*)d_in[5];
    const float* inw  = (const float*)d_in[6];
    const float* inb  = (const float*)d_in[7];
    const float* ow   = (const float*)d_in[8];
    const float* ob   = (const float*)d_in[9];
    const float* W1   = (const float*)d_in[10];
    const float* b1   = (const float*)d_in[11];
    const float* W2   = (const float*)d_in[12];
    const float* b2   = (const float*)d_in[13];
    const float* g1   = (const float*)d_in[14];
    const float* be1  = (const float*)d_in[15];
    const float* g2   = (const float*)d_in[16];
    const float* be2  = (const float*)d_in[17];
    const float* Wout = (const float*)d_in[18];
    const float* bout = (const float*)d_in[19];
    float* out = (float*)d_out;

    // 1. prototype norms
    k_proto<<<1, 256>>>(prot);
    // 2. inorm + argmax + embeddings
    k_rowprep<<<1024, 256>>>(x, Wemb, bemb, Wpro, bpro);
    // 3. Q projection: IE(0) -> Q(2)   [tf32 mma + prefetch]
    k_mmagemm<0,0,128><<<dim3(TOK_/128, 2), 256>>>(0, inw, inb, 2, 128);
    // 4. fused K|V projection with virtual [IE;PE] concat -> KVO(3)
    k_mmagemm<0,1,128><<<dim3(KVN_/128, 4), 256>>>(0, inw + 128*E_, inb + 128, 3, 256);
    // 5. softmax bound prep
    k_qn<<<TOK_*H_/256, 256>>>();
    k_kmax<<<B_*H_, 256>>>();
    // 6. attention (tf32 tensor cores)
    k_attn<<<B_*H_*2, 128>>>();
    // 7. out_proj: AT(4) -> AP(5)
    k_mmagemm<0,0,128><<<dim3(TOK_/128, 2), 256>>>(4, ow, ob, 5, 128);
    // 8. h1 = LN(IE + AP)
    k_lnres<<<TOK_/8, 256>>>(0, 5, g1, be1, 6);
    // 9. ffn1 = relu(h1 @ W1^T + b1): H1(6) -> F1(7)
    k_mmagemm<1,0,128><<<dim3(TOK_/128, 1), 256>>>(6, W1, b1, 7, 64);
    // 10. ffn2: F1(7) -> F2(8)  [K=64]
    k_mmagemm<0,0,64><<<dim3(TOK_/128, 2), 256>>>(7, W2, b2, 8, 128);
    // 11. z = LN(h1 + ffn2)
    k_lnres<<<TOK_/8, 256>>>(6, 8, g2, be2, 9);
    // 12. final projection split-K + reduce (fp32)
    k_splitk<<<KCHUNKS_, 256>>>(Wout);
    k_reduce<<<8, 256>>>(bout, out);
}

// round 9
// speedup vs baseline: 1.7894x; 1.1482x over previous
#include <cuda_runtime.h>

// ---------------- problem constants ----------------
#define B_      16
#define N_      64
#define P_      6
#define D_      8
#define E_      128
#define H_      8
#define HD_     16
#define S_      512            // N*D tokens per batch
#define TOK_    (B_*S_)        // 8192
#define KVN_    (B_*2*S_)      // 16384
#define NPROTO_ 256            // D * 32 prototype rows
#define I_      64
#define O_      128
#define KOUT_   (S_*E_)        // 65536
#define KCHUNKS_ 128
#define KCSZ_   (KOUT_/KCHUNKS_) // 512

// ---------------- device scratch (no allocations allowed) ----------------
__device__ float g_PN  [NPROTO_*P_];
__device__ float g_PNL2[NPROTO_*P_];
__device__ float g_IE  [TOK_*E_];
__device__ float g_PE  [TOK_*E_];
__device__ float g_Q   [TOK_*E_];
__device__ float g_KVO [KVN_*2*E_];   // cols 0..127 = K, 128..255 = V
__device__ float g_AT  [TOK_*E_];
__device__ float g_AP  [TOK_*E_];
__device__ float g_H1  [TOK_*E_];
__device__ float g_F1  [TOK_*I_];
__device__ float g_F2  [TOK_*E_];
__device__ float g_Z   [TOK_*E_];
__device__ float g_PART[KCHUNKS_*B_*O_];
__device__ float g_QN  [TOK_*H_];     // per (qrow, head) L2 norm
__device__ float g_KMAX[B_*H_];       // per (b, head) max key L2 norm

__device__ __forceinline__ float* bufptr(int id){
    switch(id){
        case 0: return g_IE;
        case 2: return g_Q;
        case 3: return g_KVO;
        case 4: return g_AT;
        case 5: return g_AP;
        case 6: return g_H1;
        case 7: return g_F1;
        case 8: return g_F2;
        default: return g_Z;
    }
}

// ---------------- tf32 helpers ----------------
__device__ __forceinline__ unsigned f2tf(float f){
    unsigned r; asm("cvt.rna.tf32.f32 %0, %1;" : "=r"(r) : "f"(f)); return r;
}
__device__ __forceinline__ void mma_tf32(float c[4], const unsigned a[4], const unsigned b[2]){
    asm volatile("mma.sync.aligned.m16n8k8.row.col.f32.tf32.tf32.f32 "
        "{%0,%1,%2,%3}, {%4,%5,%6,%7}, {%8,%9}, {%0,%1,%2,%3};"
        : "+f"(c[0]), "+f"(c[1]), "+f"(c[2]), "+f"(c[3])
        : "r"(a[0]), "r"(a[1]), "r"(a[2]), "r"(a[3]), "r"(b[0]), "r"(b[1]));
}

// ---------------- prototype instance-norm + L2 ----------------
__global__ void k_proto(const float* __restrict__ proto){
    int t = threadIdx.x;
    if (t >= NPROTO_) return;
    float v[P_]; float s = 0.f;
    #pragma unroll
    for (int p = 0; p < P_; p++){ v[p] = proto[t*P_ + p]; s += v[p]; }
    float m = s * (1.f/P_);
    float var = 0.f;
    #pragma unroll
    for (int p = 0; p < P_; p++){ float d = v[p]-m; var += d*d; }
    var *= (1.f/P_);
    float rs = rsqrtf(var + 1e-5f);
    float nrm = 0.f;
    #pragma unroll
    for (int p = 0; p < P_; p++){ v[p] = (v[p]-m)*rs; nrm += v[p]*v[p]; g_PN[t*P_+p] = v[p]; }
    float inv = 1.f / fmaxf(sqrtf(nrm), 1e-12f);
    #pragma unroll
    for (int p = 0; p < P_; p++) g_PNL2[t*P_+p] = v[p]*inv;
}

// ---------------- per-row inorm + argmax lookup + both embeddings ----------------
__global__ void k_rowprep(const float* __restrict__ x,
                          const float* __restrict__ Wemb, const float* __restrict__ bemb,
                          const float* __restrict__ Wpro, const float* __restrict__ bpro){
    __shared__ float sPN  [NPROTO_*P_];
    __shared__ float sPNL2[NPROTO_*P_];
    __shared__ float sWe[E_*P_];
    __shared__ float sWp[E_*P_];
    __shared__ float sbe[E_];
    __shared__ float sbp[E_];
    int tid = threadIdx.x;
    for (int i = tid; i < NPROTO_*P_; i += 256){ sPN[i] = g_PN[i]; sPNL2[i] = g_PNL2[i]; }
    for (int i = tid; i < E_*P_;     i += 256){ sWe[i] = Wemb[i];  sWp[i]  = Wpro[i]; }
    if (tid < E_){ sbe[tid] = bemb[tid]; sbp[tid] = bpro[tid]; }
    __syncthreads();

    int warp = tid >> 5, lane = tid & 31;
    int r = blockIdx.x*8 + warp;
    int b = r >> 9; int n = (r >> 3) & 63; int d = r & 7;
    const float* xp = x + ((b*64 + n)*6)*8 + d;

    float v[6]; float s = 0.f;
    #pragma unroll
    for (int p = 0; p < 6; p++){ v[p] = xp[p*8]; s += v[p]; }
    float mean = s * (1.f/6.f);
    float var = 0.f;
    #pragma unroll
    for (int p = 0; p < 6; p++){ float dd = v[p]-mean; var += dd*dd; }
    var *= (1.f/6.f);
    float rs = rsqrtf(var + 1e-5f);
    float xn[6];
    #pragma unroll
    for (int p = 0; p < 6; p++) xn[p] = (v[p]-mean)*rs;

    float best = -1e30f; int bi = 0;
    #pragma unroll
    for (int i = 0; i < 8; i++){
        int pidx = i*32 + lane;
        const float* pr = &sPNL2[pidx*6];
        float sim = xn[0]*pr[0] + xn[1]*pr[1] + xn[2]*pr[2]
                  + xn[3]*pr[3] + xn[4]*pr[4] + xn[5]*pr[5];
        if (sim > best){ best = sim; bi = pidx; }
    }
    #pragma unroll
    for (int off = 16; off; off >>= 1){
        float ov = __shfl_xor_sync(0xffffffffu, best, off);
        int   oi = __shfl_xor_sync(0xffffffffu, bi,   off);
        if (ov > best || (ov == best && oi < bi)){ best = ov; bi = oi; }
    }

    float sel[6];
    #pragma unroll
    for (int p = 0; p < 6; p++) sel[p] = sPN[bi*6 + p];

    #pragma unroll
    for (int e4 = 0; e4 < 4; e4++){
        int e = e4*32 + lane;
        const float* we = &sWe[e*6];
        const float* wp = &sWp[e*6];
        float a1 = sbe[e], a2 = sbp[e];
        #pragma unroll
        for (int p = 0; p < 6; p++){ a1 += xn[p]*we[p]; a2 += sel[p]*wp[p]; }
        g_IE[r*E_ + e] = a1;
        g_PE[r*E_ + e] = a2;
    }
}

// ---------------- tf32 tensor-core GEMM: C[M,Nn] = A[M,K] @ W[Nn,K]^T + bias ----
template<int RELU, int CONCAT, int KK>
__global__ void __launch_bounds__(256) k_mmagemm(int aId, const float* __restrict__ W,
                        const float* __restrict__ bias, int cId, int Nn){
    __shared__ unsigned sA[128*36];
    __shared__ unsigned sW[64*36];
    float* C = bufptr(cId);
    int t = threadIdx.x;
    int m0 = blockIdx.x * 128, n0 = blockIdx.y * 64;
    const float* Abase;
    if (CONCAT){
        int bb = m0 >> 10, j = m0 & 1023;
        Abase = ((j < 512) ? g_IE : g_PE) + (size_t)(bb*512 + (j & 511)) * KK;
    } else {
        Abase = bufptr(aId) + (size_t)m0 * KK;
    }
    int lane = t & 31, warp = t >> 5;
    int wm = warp >> 1, wn = warp & 1;
    int lq = lane >> 2, lc = lane & 3;
    int arow = t >> 3, ac4 = (t & 7)*4;

    float c[2][4][4];
    #pragma unroll
    for (int mt = 0; mt < 2; mt++)
        #pragma unroll
        for (int nt = 0; nt < 4; nt++)
            c[mt][nt][0]=c[mt][nt][1]=c[mt][nt][2]=c[mt][nt][3]=0.f;

    float4 pa[4], pw[2];
    #pragma unroll
    for (int i = 0; i < 4; i++)
        pa[i] = *(const float4*)&Abase[(size_t)(arow + i*32)*KK + ac4];
    #pragma unroll
    for (int i = 0; i < 2; i++)
        pw[i] = *(const float4*)&W[(size_t)(n0 + arow + i*32)*KK + ac4];

    for (int k0 = 0; k0 < KK; k0 += 32){
        #pragma unroll
        for (int i = 0; i < 4; i++){
            unsigned* d = &sA[(arow + i*32)*36 + ac4];
            d[0]=f2tf(pa[i].x); d[1]=f2tf(pa[i].y); d[2]=f2tf(pa[i].z); d[3]=f2tf(pa[i].w);
        }
        #pragma unroll
        for (int i = 0; i < 2; i++){
            unsigned* d = &sW[(arow + i*32)*36 + ac4];
            d[0]=f2tf(pw[i].x); d[1]=f2tf(pw[i].y); d[2]=f2tf(pw[i].z); d[3]=f2tf(pw[i].w);
        }
        __syncthreads();
        if (k0 + 32 < KK){
            #pragma unroll
            for (int i = 0; i < 4; i++)
                pa[i] = *(const float4*)&Abase[(size_t)(arow + i*32)*KK + k0 + 32 + ac4];
            #pragma unroll
            for (int i = 0; i < 2; i++)
                pw[i] = *(const float4*)&W[(size_t)(n0 + arow + i*32)*KK + k0 + 32 + ac4];
        }
        #pragma unroll
        for (int ks = 0; ks < 4; ks++){
            int k = ks*8;
            unsigned a[2][4], bf[4][2];
            #pragma unroll
            for (int mt = 0; mt < 2; mt++){
                int r = wm*32 + mt*16 + lq;
                a[mt][0] = sA[r*36 + k + lc];
                a[mt][1] = sA[(r+8)*36 + k + lc];
                a[mt][2] = sA[r*36 + k + lc + 4];
                a[mt][3] = sA[(r+8)*36 + k + lc + 4];
            }
            #pragma unroll
            for (int nt = 0; nt < 4; nt++){
                int n = wn*32 + nt*8 + lq;
                bf[nt][0] = sW[n*36 + k + lc];
                bf[nt][1] = sW[n*36 + k + lc + 4];
            }
            #pragma unroll
            for (int mt = 0; mt < 2; mt++)
                #pragma unroll
                for (int nt = 0; nt < 4; nt++)
                    mma_tf32(c[mt][nt], a[mt], bf[nt]);
        }
        __syncthreads();
    }
    #pragma unroll
    for (int nt = 0; nt < 4; nt++){
        int col = n0 + wn*32 + nt*8 + 2*lc;
        float b0 = bias[col], b1 = bias[col+1];
        #pragma unroll
        for (int mt = 0; mt < 2; mt++){
            int row = m0 + wm*32 + mt*16 + lq;
            float v0 = c[mt][nt][0] + b0, v1 = c[mt][nt][1] + b1;
            float v2 = c[mt][nt][2] + b0, v3 = c[mt][nt][3] + b1;
            if (RELU){
                v0 = fmaxf(v0,0.f); v1 = fmaxf(v1,0.f);
                v2 = fmaxf(v2,0.f); v3 = fmaxf(v3,0.f);
            }
            *(float2*)&C[(size_t)row*Nn + col]     = make_float2(v0, v1);
            *(float2*)&C[(size_t)(row+8)*Nn + col] = make_float2(v2, v3);
        }
    }
}

// ---------------- per (qrow, head) L2 norm of q ----------------
__global__ void k_qn(){
    int i = blockIdx.x*256 + threadIdx.x;      // 0..65535 = row*8+h
    int row = i >> 3, h = i & 7;
    const float4* q = (const float4*)(g_Q + (size_t)row*E_ + h*16);
    float4 a = q[0], b = q[1], c = q[2], d = q[3];
    float s = a.x*a.x+a.y*a.y+a.z*a.z+a.w*a.w
            + b.x*b.x+b.y*b.y+b.z*b.z+b.w*b.w
            + c.x*c.x+c.y*c.y+c.z*c.z+c.w*c.w
            + d.x*d.x+d.y*d.y+d.z*d.z+d.w*d.w;
    g_QN[i] = sqrtf(s);
}

// ---------------- per (b, head) max key L2 norm ----------------
__global__ void k_kmax(){
    int bh = blockIdx.x; int b = bh >> 3, h = bh & 7;
    const float* base = g_KVO + (size_t)(b*1024)*256 + h*16;
    float mx = 0.f;
    for (int j = threadIdx.x; j < 1024; j += 256){
        const float4* kp = (const float4*)(base + (size_t)j*256);
        float4 a = kp[0], bb = kp[1], c = kp[2], d = kp[3];
        float s = a.x*a.x+a.y*a.y+a.z*a.z+a.w*a.w
                + bb.x*bb.x+bb.y*bb.y+bb.z*bb.z+bb.w*bb.w
                + c.x*c.x+c.y*c.y+c.z*c.z+c.w*c.w
                + d.x*d.x+d.y*d.y+d.z*d.z+d.w*d.w;
        mx = fmaxf(mx, s);
    }
    #pragma unroll
    for (int off = 16; off; off >>= 1)
        mx = fmaxf(mx, __shfl_xor_sync(0xffffffffu, mx, off));
    __shared__ float red[8];
    if ((threadIdx.x & 31) == 0) red[threadIdx.x >> 5] = mx;
    __syncthreads();
    if (threadIdx.x == 0){
        float m = red[0];
        #pragma unroll
        for (int w = 1; w < 8; w++) m = fmaxf(m, red[w]);
        g_KMAX[bh] = sqrtf(m);
    }
}

// ---------------- attention v2: 8 warps/block, smem-staged KV tiles ----------
__global__ void __launch_bounds__(256) k_attn(){
    __shared__ float sK[16*20];
    __shared__ float sV[16*24];
    int blk = blockIdx.x;                 // 0..255
    int bh = blk >> 1, qh = blk & 1;
    int b = bh >> 3, h = bh & 7;
    int t = threadIdx.x;
    int lane = t & 31, warp = t >> 5;
    int lq = lane >> 2, lc = lane & 3;
    int qrow0 = b*512 + qh*256 + warp*32; // 32 q rows per warp
    int hoff = h*16;
    const float* Qb  = g_Q  + (size_t)qrow0*E_ + hoff;
    const float* KVb = g_KVO + (size_t)(b*1024)*256;

    unsigned qa[2][2][4];
    #pragma unroll
    for (int mt = 0; mt < 2; mt++)
        #pragma unroll
        for (int ks = 0; ks < 2; ks++){
            const float* qp = Qb + (size_t)(mt*16)*E_ + ks*8;
            qa[mt][ks][0] = f2tf(qp[(size_t)lq*E_     + lc]);
            qa[mt][ks][1] = f2tf(qp[(size_t)(lq+8)*E_ + lc]);
            qa[mt][ks][2] = f2tf(qp[(size_t)lq*E_     + lc+4]);
            qa[mt][ks][3] = f2tf(qp[(size_t)(lq+8)*E_ + lc+4]);
        }

    float kmax = g_KMAX[bh];
    float mb[2][2];
    #pragma unroll
    for (int mt = 0; mt < 2; mt++){
        mb[mt][0] = g_QN[(qrow0 + mt*16 + lq  )*8 + h] * kmax * 0.25f;
        mb[mt][1] = g_QN[(qrow0 + mt*16 + lq+8)*8 + h] * kmax * 0.25f;
    }

    float o[2][2][4];
    #pragma unroll
    for (int mt = 0; mt < 2; mt++)
        #pragma unroll
        for (int d = 0; d < 2; d++)
            o[mt][d][0]=o[mt][d][1]=o[mt][d][2]=o[mt][d][3]=0.f;
    float lsum[2][2] = {};

    int s1 = (lane & 28) | (lc >> 1);
    int s2 = s1 + 2;
    bool odd = lc & 1;

    int sj = t >> 3, sf = t & 7;
    int scol = (sf & 3)*4;

    #pragma unroll 1
    for (int key0 = 0; key0 < 1024; key0 += 16){
        if (t < 128){
            const float* src = KVb + (size_t)(key0 + sj)*256 +
                               ((sf < 4) ? (hoff + scol) : (128 + hoff + scol));
            float4 v = *(const float4*)src;
            float* dst = (sf < 4) ? &sK[sj*20 + scol] : &sV[sj*24 + scol];
            *(float4*)dst = v;
        }
        __syncthreads();

        unsigned kb[2][2][2];
        #pragma unroll
        for (int nt = 0; nt < 2; nt++)
            #pragma unroll
            for (int ks = 0; ks < 2; ks++){
                const float* kp = &sK[(nt*8 + lq)*20 + ks*8 + lc];
                kb[nt][ks][0] = f2tf(kp[0]);
                kb[nt][ks][1] = f2tf(kp[4]);
            }
        float s[2][2][4];
        #pragma unroll
        for (int mt = 0; mt < 2; mt++)
            #pragma unroll
            for (int nt = 0; nt < 2; nt++){
                s[mt][nt][0]=s[mt][nt][1]=s[mt][nt][2]=s[mt][nt][3]=0.f;
                mma_tf32(s[mt][nt], qa[mt][0], kb[nt][0]);
                mma_tf32(s[mt][nt], qa[mt][1], kb[nt][1]);
            }
        #pragma unroll
        for (int mt = 0; mt < 2; mt++)
            #pragma unroll
            for (int nt = 0; nt < 2; nt++){
                float p0 = __expf(s[mt][nt][0]*0.25f - mb[mt][0]);
                float p1 = __expf(s[mt][nt][1]*0.25f - mb[mt][0]);
                float p2 = __expf(s[mt][nt][2]*0.25f - mb[mt][1]);
                float p3 = __expf(s[mt][nt][3]*0.25f - mb[mt][1]);
                float q0 = __uint_as_float(f2tf(p0));
                float q1 = __uint_as_float(f2tf(p1));
                float q2 = __uint_as_float(f2tf(p2));
                float q3 = __uint_as_float(f2tf(p3));
                s[mt][nt][0]=q0; s[mt][nt][1]=q1; s[mt][nt][2]=q2; s[mt][nt][3]=q3;
                lsum[mt][0] += q0 + q1;
                lsum[mt][1] += q2 + q3;
            }
        unsigned vb[2][2][2];
        #pragma unroll
        for (int kt = 0; kt < 2; kt++)
            #pragma unroll
            for (int d = 0; d < 2; d++){
                const float* vp = &sV[(kt*8 + lc)*24 + d*8 + lq];
                vb[kt][d][0] = f2tf(vp[0]);
                vb[kt][d][1] = f2tf(vp[4*24]);
            }
        #pragma unroll
        for (int mt = 0; mt < 2; mt++)
            #pragma unroll
            for (int kt = 0; kt < 2; kt++){
                unsigned a[4];
                float w0 = __shfl_sync(0xffffffffu, s[mt][kt][0], s1);
                float w1 = __shfl_sync(0xffffffffu, s[mt][kt][1], s1);
                a[0] = __float_as_uint(odd ? w1 : w0);
                float w2 = __shfl_sync(0xffffffffu, s[mt][kt][2], s1);
                float w3 = __shfl_sync(0xffffffffu, s[mt][kt][3], s1);
                a[1] = __float_as_uint(odd ? w3 : w2);
                w0 = __shfl_sync(0xffffffffu, s[mt][kt][0], s2);
                w1 = __shfl_sync(0xffffffffu, s[mt][kt][1], s2);
                a[2] = __float_as_uint(odd ? w1 : w0);
                w2 = __shfl_sync(0xffffffffu, s[mt][kt][2], s2);
                w3 = __shfl_sync(0xffffffffu, s[mt][kt][3], s2);
                a[3] = __float_as_uint(odd ? w3 : w2);
                mma_tf32(o[mt][0], a, vb[kt][0]);
                mma_tf32(o[mt][1], a, vb[kt][1]);
            }
        __syncthreads();
    }

    float inv[2][2];
    #pragma unroll
    for (int mt = 0; mt < 2; mt++)
        #pragma unroll
        for (int hf = 0; hf < 2; hf++){
            float l = lsum[mt][hf];
            l += __shfl_xor_sync(0xffffffffu, l, 1);
            l += __shfl_xor_sync(0xffffffffu, l, 2);
            inv[mt][hf] = 1.f / l;
        }
    #pragma unroll
    for (int mt = 0; mt < 2; mt++)
        #pragma unroll
        for (int d = 0; d < 2; d++){
            float* op = g_AT + (size_t)(qrow0 + mt*16 + lq)*E_ + hoff + d*8 + 2*lc;
            *(float2*)op = make_float2(o[mt][d][0]*inv[mt][0], o[mt][d][1]*inv[mt][0]);
            *(float2*)(op + 8*E_) = make_float2(o[mt][d][2]*inv[mt][1], o[mt][d][3]*inv[mt][1]);
        }
}

// ---------------- residual + LayerNorm (row = 128) ----------------
__global__ void k_lnres(int aId, int rId, const float* __restrict__ g,
                        const float* __restrict__ be, int oId){
    const float* A = bufptr(aId);
    const float* R = bufptr(rId);
    float* out = bufptr(oId);
    int tid = threadIdx.x; int warp = tid >> 5, lane = tid & 31;
    int row = blockIdx.x*8 + warp;
    float v[4];
    #pragma unroll
    for (int i = 0; i < 4; i++){
        int e = i*32 + lane;
        v[i] = A[(size_t)row*E_ + e] + R[(size_t)row*E_ + e];
    }
    float s  = v[0]+v[1]+v[2]+v[3];
    float s2 = v[0]*v[0]+v[1]*v[1]+v[2]*v[2]+v[3]*v[3];
    #pragma unroll
    for (int off = 16; off; off >>= 1){
        s  += __shfl_xor_sync(0xffffffffu, s,  off);
        s2 += __shfl_xor_sync(0xffffffffu, s2, off);
    }
    float mean = s * (1.f/128.f);
    float var  = s2 * (1.f/128.f) - mean*mean;
    float rs = rsqrtf(var + 1e-5f);
    #pragma unroll
    for (int i = 0; i < 4; i++){
        int e = i*32 + lane;
        out[(size_t)row*E_ + e] = (v[i]-mean)*rs*g[e] + be[e];
    }
}

// ---------------- final projection: split-K over 65536 (fp32 for accuracy) ----
__global__ void k_splitk(const float* __restrict__ W){
    __shared__ float Zs[16*32];
    __shared__ float Ws_[32*129];
    int t = threadIdx.x;
    int kb = blockIdx.x * KCSZ_;
    int o = t & 127;
    int bset = t >> 7;
    float acc[8];
    #pragma unroll
    for (int i = 0; i < 8; i++) acc[i] = 0.f;
    for (int k0 = 0; k0 < KCSZ_; k0 += 32){
        #pragma unroll
        for (int i = 0; i < 2; i++){
            int e = t + i*256; int b_ = e >> 5, kk = e & 31;
            Zs[b_*32 + kk] = g_Z[(size_t)b_*KOUT_ + kb + k0 + kk];
        }
        #pragma unroll
        for (int i = 0; i < 16; i++){
            int e = t + i*256; int oo = e >> 5, kk = e & 31;
            Ws_[kk*129 + oo] = W[(size_t)oo*KOUT_ + kb + k0 + kk];
        }
        __syncthreads();
        #pragma unroll
        for (int kk = 0; kk < 32; kk++){
            float w = Ws_[kk*129 + o];
            #pragma unroll
            for (int i = 0; i < 8; i++)
                acc[i] += Zs[(bset*8 + i)*32 + kk] * w;
        }
        __syncthreads();
    }
    #pragma unroll
    for (int i = 0; i < 8; i++)
        g_PART[blockIdx.x*2048 + (bset*8 + i)*128 + o] = acc[i];
}

__global__ void k_reduce(const float* __restrict__ bout, float* __restrict__ out){
    int e = blockIdx.x*256 + threadIdx.x;   // 0..2047
    float s = bout[e & 127];
    #pragma unroll 8
    for (int c = 0; c < KCHUNKS_; c++) s += g_PART[c*2048 + e];
    out[e] = s;
}

// ---------------- launch ----------------
extern "C" void kernel_launch(void* const* d_in, const int* in_sizes, int n_in,
                              void* d_out, int out_size){
    const float* x    = (const float*)d_in[0];
    const float* prot = (const float*)d_in[1];
    const float* Wemb = (const float*)d_in[2];
    const float* bemb = (const float*)d_in[3];
    const float* Wpro = (const float*)d_in[4];
    const float* bpro = (const float*)d_in[5];
    const float* inw  = (const float*)d_in[6];
    const float* inb  = (const float*)d_in[7];
    const float* ow   = (const float*)d_in[8];
    const float* ob   = (const float*)d_in[9];
    const float* W1   = (const float*)d_in[10];
    const float* b1   = (const float*)d_in[11];
    const float* W2   = (const float*)d_in[12];
    const float* b2   = (const float*)d_in[13];
    const float* g1   = (const float*)d_in[14];
    const float* be1  = (const float*)d_in[15];
    const float* g2   = (const float*)d_in[16];
    const float* be2  = (const float*)d_in[17];
    const float* Wout = (const float*)d_in[18];
    const float* bout = (const float*)d_in[19];
    float* out = (float*)d_out;

    k_proto<<<1, 256>>>(prot);
    k_rowprep<<<1024, 256>>>(x, Wemb, bemb, Wpro, bpro);
    k_mmagemm<0,0,128><<<dim3(TOK_/128, 2), 256>>>(0, inw, inb, 2, 128);
    k_mmagemm<0,1,128><<<dim3(KVN_/128, 4), 256>>>(0, inw + 128*E_, inb + 128, 3, 256);
    k_qn<<<TOK_*H_/256, 256>>>();
    k_kmax<<<B_*H_, 256>>>();
    k_attn<<<B_*H_*2, 256>>>();
    k_mmagemm<0,0,128><<<dim3(TOK_/128, 2), 256>>>(4, ow, ob, 5, 128);
    k_lnres<<<TOK_/8, 256>>>(0, 5, g1, be1, 6);
    k_mmagemm<1,0,128><<<dim3(TOK_/128, 1), 256>>>(6, W1, b1, 7, 64);
    k_mmagemm<0,0,64><<<dim3(TOK_/128, 2), 256>>>(7, W2, b2, 8, 128);
    k_lnres<<<TOK_/8, 256>>>(6, 8, g2, be2, 9);
    k_splitk<<<KCHUNKS_, 256>>>(Wout);
    k_reduce<<<8, 256>>>(bout, out);
}

// round 10
// speedup vs baseline: 2.0314x; 1.1352x over previous
#include <cuda_runtime.h>

// ---------------- problem constants ----------------
#define B_      16
#define N_      64
#define P_      6
#define D_      8
#define E_      128
#define H_      8
#define HD_     16
#define S_      512            // N*D tokens per batch
#define TOK_    (B_*S_)        // 8192
#define KVN_    (B_*2*S_)      // 16384
#define NPROTO_ 256            // D * 32 prototype rows
#define I_      64
#define O_      128
#define KOUT_   (S_*E_)        // 65536
#define KCHUNKS_ 256
#define KCSZ_   (KOUT_/KCHUNKS_) // 256

// ---------------- device scratch (no allocations allowed) ----------------
__device__ float g_IE  [TOK_*E_];
__device__ float g_PE  [TOK_*E_];
__device__ float g_Q   [TOK_*E_];
__device__ float g_KVO [KVN_*2*E_];   // cols 0..127 = K, 128..255 = V
__device__ float g_AT  [TOK_*E_];
__device__ float g_AP  [TOK_*E_];
__device__ float g_H1  [TOK_*E_];
__device__ float g_F1  [TOK_*I_];
__device__ float g_F2  [TOK_*E_];
__device__ float g_Z   [TOK_*E_];
__device__ float g_PART[KCHUNKS_*B_*O_];
__device__ float g_QN  [TOK_*H_];     // per (qrow, head) L2 norm
__device__ float g_KMAX[B_*H_];       // per (b, head) max key L2 norm

__device__ __forceinline__ float* bufptr(int id){
    switch(id){
        case 0: return g_IE;
        case 2: return g_Q;
        case 3: return g_KVO;
        case 4: return g_AT;
        case 5: return g_AP;
        case 6: return g_H1;
        case 7: return g_F1;
        case 8: return g_F2;
        default: return g_Z;
    }
}

// ---------------- tf32 helpers ----------------
__device__ __forceinline__ unsigned f2tf(float f){
    unsigned r; asm("cvt.rna.tf32.f32 %0, %1;" : "=r"(r) : "f"(f)); return r;
}
__device__ __forceinline__ void mma_tf32(float c[4], const unsigned a[4], const unsigned b[2]){
    asm volatile("mma.sync.aligned.m16n8k8.row.col.f32.tf32.tf32.f32 "
        "{%0,%1,%2,%3}, {%4,%5,%6,%7}, {%8,%9}, {%0,%1,%2,%3};"
        : "+f"(c[0]), "+f"(c[1]), "+f"(c[2]), "+f"(c[3])
        : "r"(a[0]), "r"(a[1]), "r"(a[2]), "r"(a[3]), "r"(b[0]), "r"(b[1]));
}

// ---------------- rowprep: proto inorm (in-block) + x inorm + argmax + embeds ----
__global__ void k_rowprep(const float* __restrict__ x, const float* __restrict__ proto,
                          const float* __restrict__ Wemb, const float* __restrict__ bemb,
                          const float* __restrict__ Wpro, const float* __restrict__ bpro){
    __shared__ float sPN  [NPROTO_*P_];
    __shared__ float sPNL2[NPROTO_*P_];
    __shared__ float sWe[E_*P_];
    __shared__ float sWp[E_*P_];
    __shared__ float sbe[E_];
    __shared__ float sbp[E_];
    int tid = threadIdx.x;
    // prototype inorm + l2 (each block recomputes; 256 threads, 1 proto each)
    {
        float v[P_]; float s = 0.f;
        #pragma unroll
        for (int p = 0; p < P_; p++){ v[p] = proto[tid*P_ + p]; s += v[p]; }
        float m = s * (1.f/P_);
        float var = 0.f;
        #pragma unroll
        for (int p = 0; p < P_; p++){ float dd = v[p]-m; var += dd*dd; }
        var *= (1.f/P_);
        float rs = rsqrtf(var + 1e-5f);
        float nrm = 0.f;
        #pragma unroll
        for (int p = 0; p < P_; p++){ v[p] = (v[p]-m)*rs; nrm += v[p]*v[p]; sPN[tid*P_+p] = v[p]; }
        float inv = 1.f / fmaxf(sqrtf(nrm), 1e-12f);
        #pragma unroll
        for (int p = 0; p < P_; p++) sPNL2[tid*P_+p] = v[p]*inv;
    }
    for (int i = tid; i < E_*P_; i += 256){ sWe[i] = Wemb[i]; sWp[i] = Wpro[i]; }
    if (tid < E_){ sbe[tid] = bemb[tid]; sbp[tid] = bpro[tid]; }
    __syncthreads();

    int warp = tid >> 5, lane = tid & 31;
    int r = blockIdx.x*8 + warp;
    int b = r >> 9; int n = (r >> 3) & 63; int d = r & 7;
    const float* xp = x + ((b*64 + n)*6)*8 + d;

    float v[6]; float s = 0.f;
    #pragma unroll
    for (int p = 0; p < 6; p++){ v[p] = xp[p*8]; s += v[p]; }
    float mean = s * (1.f/6.f);
    float var = 0.f;
    #pragma unroll
    for (int p = 0; p < 6; p++){ float dd = v[p]-mean; var += dd*dd; }
    var *= (1.f/6.f);
    float rs = rsqrtf(var + 1e-5f);
    float xn[6];
    #pragma unroll
    for (int p = 0; p < 6; p++) xn[p] = (v[p]-mean)*rs;

    float best = -1e30f; int bi = 0;
    #pragma unroll
    for (int i = 0; i < 8; i++){
        int pidx = i*32 + lane;
        const float* pr = &sPNL2[pidx*6];
        float sim = xn[0]*pr[0] + xn[1]*pr[1] + xn[2]*pr[2]
                  + xn[3]*pr[3] + xn[4]*pr[4] + xn[5]*pr[5];
        if (sim > best){ best = sim; bi = pidx; }
    }
    #pragma unroll
    for (int off = 16; off; off >>= 1){
        float ov = __shfl_xor_sync(0xffffffffu, best, off);
        int   oi = __shfl_xor_sync(0xffffffffu, bi,   off);
        if (ov > best || (ov == best && oi < bi)){ best = ov; bi = oi; }
    }

    float sel[6];
    #pragma unroll
    for (int p = 0; p < 6; p++) sel[p] = sPN[bi*6 + p];

    #pragma unroll
    for (int e4 = 0; e4 < 4; e4++){
        int e = e4*32 + lane;
        const float* we = &sWe[e*6];
        const float* wp = &sWp[e*6];
        float a1 = sbe[e], a2 = sbp[e];
        #pragma unroll
        for (int p = 0; p < 6; p++){ a1 += xn[p]*we[p]; a2 += sel[p]*wp[p]; }
        g_IE[r*E_ + e] = a1;
        g_PE[r*E_ + e] = a2;
    }
}

// ---------------- tf32 tensor-core GEMM, fragment-major smem ------------------
// block 256 thr / 8 warps, tile 128M x 64N, warp 32x32.
// sA: [8 mtile x 4 ks] frags, stride 132; thread frag = one LDS.128.
// sW: [8 ntile x 4 ks] frags, stride 66;  thread frag = one LDS.64.
template<int RELU, int CONCAT, int KK>
__global__ void __launch_bounds__(256) k_mmagemm(int aId, const float* __restrict__ W,
                        const float* __restrict__ bias, int cId, int Nn){
    __shared__ __align__(16) unsigned sA[32*132];
    __shared__ __align__(16) unsigned sW[32*66];
    float* C = bufptr(cId);
    int t = threadIdx.x;
    int m0 = blockIdx.x * 128, n0 = blockIdx.y * 64;
    const float* Abase;
    if (CONCAT){
        int bb = m0 >> 10, j = m0 & 1023;
        Abase = ((j < 512) ? g_IE : g_PE) + (size_t)(bb*512 + (j & 511)) * KK;
    } else {
        Abase = bufptr(aId) + (size_t)m0 * KK;
    }
    int lane = t & 31, warp = t >> 5;
    int wm = warp >> 1, wn = warp & 1;
    int lq = lane >> 2, lc = lane & 3;
    int arow = t >> 3, ac4 = (t & 7)*4;
    int ksld = ac4 >> 3;                 // k-step of this thread's staged float4
    int aslot = 2*((ac4 >> 2) & 1);      // +0/2 depending on k half
    int bslot = (ac4 >> 2) & 1;

    float c[2][4][4];
    #pragma unroll
    for (int mt = 0; mt < 2; mt++)
        #pragma unroll
        for (int nt = 0; nt < 4; nt++)
            c[mt][nt][0]=c[mt][nt][1]=c[mt][nt][2]=c[mt][nt][3]=0.f;

    float4 pa[4], pw[2];
    #pragma unroll
    for (int i = 0; i < 4; i++)
        pa[i] = *(const float4*)&Abase[(size_t)(arow + i*32)*KK + ac4];
    #pragma unroll
    for (int i = 0; i < 2; i++)
        pw[i] = *(const float4*)&W[(size_t)(n0 + arow + i*32)*KK + ac4];

    for (int k0 = 0; k0 < KK; k0 += 32){
        #pragma unroll
        for (int i = 0; i < 4; i++){
            int row = arow + i*32;
            int fa = (row >> 4)*4 + ksld;
            unsigned* d = &sA[fa*132 + (row & 7)*16 + ((row >> 3) & 1) + aslot];
            d[0]=f2tf(pa[i].x); d[4]=f2tf(pa[i].y); d[8]=f2tf(pa[i].z); d[12]=f2tf(pa[i].w);
        }
        #pragma unroll
        for (int i = 0; i < 2; i++){
            int row = arow + i*32;
            int fb = (row >> 3)*4 + ksld;
            unsigned* d = &sW[fb*66 + (row & 7)*8 + bslot];
            d[0]=f2tf(pw[i].x); d[2]=f2tf(pw[i].y); d[4]=f2tf(pw[i].z); d[6]=f2tf(pw[i].w);
        }
        __syncthreads();
        if (k0 + 32 < KK){
            #pragma unroll
            for (int i = 0; i < 4; i++)
                pa[i] = *(const float4*)&Abase[(size_t)(arow + i*32)*KK + k0 + 32 + ac4];
            #pragma unroll
            for (int i = 0; i < 2; i++)
                pw[i] = *(const float4*)&W[(size_t)(n0 + arow + i*32)*KK + k0 + 32 + ac4];
        }
        #pragma unroll
        for (int ks = 0; ks < 4; ks++){
            unsigned a[2][4], bf[4][2];
            #pragma unroll
            for (int mt = 0; mt < 2; mt++)
                *(uint4*)a[mt] = *(const uint4*)&sA[((2*wm + mt)*4 + ks)*132 + lane*4];
            #pragma unroll
            for (int nt = 0; nt < 4; nt++)
                *(uint2*)bf[nt] = *(const uint2*)&sW[((4*wn + nt)*4 + ks)*66 + lane*2];
            #pragma unroll
            for (int mt = 0; mt < 2; mt++)
                #pragma unroll
                for (int nt = 0; nt < 4; nt++)
                    mma_tf32(c[mt][nt], a[mt], bf[nt]);
        }
        __syncthreads();
    }
    #pragma unroll
    for (int nt = 0; nt < 4; nt++){
        int col = n0 + wn*32 + nt*8 + 2*lc;
        float b0 = bias[col], b1 = bias[col+1];
        #pragma unroll
        for (int mt = 0; mt < 2; mt++){
            int row = m0 + wm*32 + mt*16 + lq;
            float v0 = c[mt][nt][0] + b0, v1 = c[mt][nt][1] + b1;
            float v2 = c[mt][nt][2] + b0, v3 = c[mt][nt][3] + b1;
            if (RELU){
                v0 = fmaxf(v0,0.f); v1 = fmaxf(v1,0.f);
                v2 = fmaxf(v2,0.f); v3 = fmaxf(v3,0.f);
            }
            *(float2*)&C[(size_t)row*Nn + col]     = make_float2(v0, v1);
            *(float2*)&C[(size_t)(row+8)*Nn + col] = make_float2(v2, v3);
        }
    }
}

// ---------------- merged qn + kmax ----------------
__global__ void k_qnkmax(){
    if (blockIdx.x < 256){
        int i = blockIdx.x*256 + threadIdx.x;  // row*8+h
        int row = i >> 3, h = i & 7;
        const float4* q = (const float4*)(g_Q + (size_t)row*E_ + h*16);
        float4 a = q[0], b = q[1], c = q[2], d = q[3];
        float s = a.x*a.x+a.y*a.y+a.z*a.z+a.w*a.w
                + b.x*b.x+b.y*b.y+b.z*b.z+b.w*b.w
                + c.x*c.x+c.y*c.y+c.z*c.z+c.w*c.w
                + d.x*d.x+d.y*d.y+d.z*d.z+d.w*d.w;
        g_QN[i] = sqrtf(s);
    } else {
        int bh = blockIdx.x - 256; int b = bh >> 3, h = bh & 7;
        const float* base = g_KVO + (size_t)(b*1024)*256 + h*16;
        float mx = 0.f;
        for (int j = threadIdx.x; j < 1024; j += 256){
            const float4* kp = (const float4*)(base + (size_t)j*256);
            float4 a = kp[0], bb = kp[1], c = kp[2], d = kp[3];
            float s = a.x*a.x+a.y*a.y+a.z*a.z+a.w*a.w
                    + bb.x*bb.x+bb.y*bb.y+bb.z*bb.z+bb.w*bb.w
                    + c.x*c.x+c.y*c.y+c.z*c.z+c.w*c.w
                    + d.x*d.x+d.y*d.y+d.z*d.z+d.w*d.w;
            mx = fmaxf(mx, s);
        }
        #pragma unroll
        for (int off = 16; off; off >>= 1)
            mx = fmaxf(mx, __shfl_xor_sync(0xffffffffu, mx, off));
        __shared__ float red[8];
        if ((threadIdx.x & 31) == 0) red[threadIdx.x >> 5] = mx;
        __syncthreads();
        if (threadIdx.x == 0){
            float m = red[0];
            #pragma unroll
            for (int w = 1; w < 8; w++) m = fmaxf(m, red[w]);
            g_KMAX[bh] = sqrtf(m);
        }
    }
}

// ---------------- attention: 8 warps/block, 32-key smem tiles -----------------
__global__ void __launch_bounds__(256) k_attn(){
    __shared__ float sK[32*20];
    __shared__ float sV[32*24];
    int blk = blockIdx.x;                 // 0..255
    int bh = blk >> 1, qh = blk & 1;
    int b = bh >> 3, h = bh & 7;
    int t = threadIdx.x;
    int lane = t & 31, warp = t >> 5;
    int lq = lane >> 2, lc = lane & 3;
    int qrow0 = b*512 + qh*256 + warp*32;
    int hoff = h*16;
    const float* Qb  = g_Q  + (size_t)qrow0*E_ + hoff;
    const float* KVb = g_KVO + (size_t)(b*1024)*256;

    unsigned qa[2][2][4];
    #pragma unroll
    for (int mt = 0; mt < 2; mt++)
        #pragma unroll
        for (int ks = 0; ks < 2; ks++){
            const float* qp = Qb + (size_t)(mt*16)*E_ + ks*8;
            qa[mt][ks][0] = f2tf(qp[(size_t)lq*E_     + lc]);
            qa[mt][ks][1] = f2tf(qp[(size_t)(lq+8)*E_ + lc]);
            qa[mt][ks][2] = f2tf(qp[(size_t)lq*E_     + lc+4]);
            qa[mt][ks][3] = f2tf(qp[(size_t)(lq+8)*E_ + lc+4]);
        }

    float kmax = g_KMAX[bh];
    float mb[2][2];
    #pragma unroll
    for (int mt = 0; mt < 2; mt++){
        mb[mt][0] = g_QN[(qrow0 + mt*16 + lq  )*8 + h] * kmax * 0.25f;
        mb[mt][1] = g_QN[(qrow0 + mt*16 + lq+8)*8 + h] * kmax * 0.25f;
    }

    float o[2][2][4];
    #pragma unroll
    for (int mt = 0; mt < 2; mt++)
        #pragma unroll
        for (int d = 0; d < 2; d++)
            o[mt][d][0]=o[mt][d][1]=o[mt][d][2]=o[mt][d][3]=0.f;
    float lsum[2][2] = {};

    int s1 = (lane & 28) | (lc >> 1);
    int s2 = s1 + 2;
    bool odd = lc & 1;

    int sj = t >> 3, sf = t & 7;          // 32 rows x 8 quarters
    int scol = (sf & 3)*4;

    #pragma unroll 1
    for (int key0 = 0; key0 < 1024; key0 += 32){
        {
            const float* src = KVb + (size_t)(key0 + sj)*256 +
                               ((sf < 4) ? (hoff + scol) : (128 + hoff + scol));
            float4 v = *(const float4*)src;
            float* dst = (sf < 4) ? &sK[sj*20 + scol] : &sV[sj*24 + scol];
            *(float4*)dst = v;
        }
        __syncthreads();

        #pragma unroll
        for (int sub = 0; sub < 2; sub++){
            int r16 = sub*16;
            unsigned kb[2][2][2];
            #pragma unroll
            for (int nt = 0; nt < 2; nt++)
                #pragma unroll
                for (int ks = 0; ks < 2; ks++){
                    const float* kp = &sK[(r16 + nt*8 + lq)*20 + ks*8 + lc];
                    kb[nt][ks][0] = f2tf(kp[0]);
                    kb[nt][ks][1] = f2tf(kp[4]);
                }
            float s[2][2][4];
            #pragma unroll
            for (int mt = 0; mt < 2; mt++)
                #pragma unroll
                for (int nt = 0; nt < 2; nt++){
                    s[mt][nt][0]=s[mt][nt][1]=s[mt][nt][2]=s[mt][nt][3]=0.f;
                    mma_tf32(s[mt][nt], qa[mt][0], kb[nt][0]);
                    mma_tf32(s[mt][nt], qa[mt][1], kb[nt][1]);
                }
            #pragma unroll
            for (int mt = 0; mt < 2; mt++)
                #pragma unroll
                for (int nt = 0; nt < 2; nt++){
                    float p0 = __expf(s[mt][nt][0]*0.25f - mb[mt][0]);
                    float p1 = __expf(s[mt][nt][1]*0.25f - mb[mt][0]);
                    float p2 = __expf(s[mt][nt][2]*0.25f - mb[mt][1]);
                    float p3 = __expf(s[mt][nt][3]*0.25f - mb[mt][1]);
                    float q0 = __uint_as_float(f2tf(p0));
                    float q1 = __uint_as_float(f2tf(p1));
                    float q2 = __uint_as_float(f2tf(p2));
                    float q3 = __uint_as_float(f2tf(p3));
                    s[mt][nt][0]=q0; s[mt][nt][1]=q1; s[mt][nt][2]=q2; s[mt][nt][3]=q3;
                    lsum[mt][0] += q0 + q1;
                    lsum[mt][1] += q2 + q3;
                }
            unsigned vb[2][2][2];
            #pragma unroll
            for (int kt = 0; kt < 2; kt++)
                #pragma unroll
                for (int d = 0; d < 2; d++){
                    const float* vp = &sV[(r16 + kt*8 + lc)*24 + d*8 + lq];
                    vb[kt][d][0] = f2tf(vp[0]);
                    vb[kt][d][1] = f2tf(vp[4*24]);
                }
            #pragma unroll
            for (int mt = 0; mt < 2; mt++)
                #pragma unroll
                for (int kt = 0; kt < 2; kt++){
                    unsigned a[4];
                    float w0 = __shfl_sync(0xffffffffu, s[mt][kt][0], s1);
                    float w1 = __shfl_sync(0xffffffffu, s[mt][kt][1], s1);
                    a[0] = __float_as_uint(odd ? w1 : w0);
                    float w2 = __shfl_sync(0xffffffffu, s[mt][kt][2], s1);
                    float w3 = __shfl_sync(0xffffffffu, s[mt][kt][3], s1);
                    a[1] = __float_as_uint(odd ? w3 : w2);
                    w0 = __shfl_sync(0xffffffffu, s[mt][kt][0], s2);
                    w1 = __shfl_sync(0xffffffffu, s[mt][kt][1], s2);
                    a[2] = __float_as_uint(odd ? w1 : w0);
                    w2 = __shfl_sync(0xffffffffu, s[mt][kt][2], s2);
                    w3 = __shfl_sync(0xffffffffu, s[mt][kt][3], s2);
                    a[3] = __float_as_uint(odd ? w3 : w2);
                    mma_tf32(o[mt][0], a, vb[kt][0]);
                    mma_tf32(o[mt][1], a, vb[kt][1]);
                }
        }
        __syncthreads();
    }

    float inv[2][2];
    #pragma unroll
    for (int mt = 0; mt < 2; mt++)
        #pragma unroll
        for (int hf = 0; hf < 2; hf++){
            float l = lsum[mt][hf];
            l += __shfl_xor_sync(0xffffffffu, l, 1);
            l += __shfl_xor_sync(0xffffffffu, l, 2);
            inv[mt][hf] = 1.f / l;
        }
    #pragma unroll
    for (int mt = 0; mt < 2; mt++)
        #pragma unroll
        for (int d = 0; d < 2; d++){
            float* op = g_AT + (size_t)(qrow0 + mt*16 + lq)*E_ + hoff + d*8 + 2*lc;
            *(float2*)op = make_float2(o[mt][d][0]*inv[mt][0], o[mt][d][1]*inv[mt][0]);
            *(float2*)(op + 8*E_) = make_float2(o[mt][d][2]*inv[mt][1], o[mt][d][3]*inv[mt][1]);
        }
}

// ---------------- residual + LayerNorm (row = 128) ----------------
__global__ void k_lnres(int aId, int rId, const float* __restrict__ g,
                        const float* __restrict__ be, int oId){
    const float* A = bufptr(aId);
    const float* R = bufptr(rId);
    float* out = bufptr(oId);
    int tid = threadIdx.x; int warp = tid >> 5, lane = tid & 31;
    int row = blockIdx.x*8 + warp;
    float v[4];
    #pragma unroll
    for (int i = 0; i < 4; i++){
        int e = i*32 + lane;
        v[i] = A[(size_t)row*E_ + e] + R[(size_t)row*E_ + e];
    }
    float s  = v[0]+v[1]+v[2]+v[3];
    float s2 = v[0]*v[0]+v[1]*v[1]+v[2]*v[2]+v[3]*v[3];
    #pragma unroll
    for (int off = 16; off; off >>= 1){
        s  += __shfl_xor_sync(0xffffffffu, s,  off);
        s2 += __shfl_xor_sync(0xffffffffu, s2, off);
    }
    float mean = s * (1.f/128.f);
    float var  = s2 * (1.f/128.f) - mean*mean;
    float rs = rsqrtf(var + 1e-5f);
    #pragma unroll
    for (int i = 0; i < 4; i++){
        int e = i*32 + lane;
        out[(size_t)row*E_ + e] = (v[i]-mean)*rs*g[e] + be[e];
    }
}

// ---------------- final projection: split-K over 65536 (fp32) -----------------
__global__ void k_splitk(const float* __restrict__ W){
    __shared__ float Zs[16*32];
    __shared__ float Ws_[32*129];
    int t = threadIdx.x;
    int kb = blockIdx.x * KCSZ_;
    int o = t & 127;
    int bset = t >> 7;
    float acc[8];
    #pragma unroll
    for (int i = 0; i < 8; i++) acc[i] = 0.f;
    for (int k0 = 0; k0 < KCSZ_; k0 += 32){
        #pragma unroll
        for (int i = 0; i < 2; i++){
            int e = t + i*256; int b_ = e >> 5, kk = e & 31;
            Zs[b_*32 + kk] = g_Z[(size_t)b_*KOUT_ + kb + k0 + kk];
        }
        #pragma unroll
        for (int i = 0; i < 16; i++){
            int e = t + i*256; int oo = e >> 5, kk = e & 31;
            Ws_[kk*129 + oo] = W[(size_t)oo*KOUT_ + kb + k0 + kk];
        }
        __syncthreads();
        #pragma unroll
        for (int kk = 0; kk < 32; kk++){
            float w = Ws_[kk*129 + o];
            #pragma unroll
            for (int i = 0; i < 8; i++)
                acc[i] += Zs[(bset*8 + i)*32 + kk] * w;
        }
        __syncthreads();
    }
    #pragma unroll
    for (int i = 0; i < 8; i++)
        g_PART[blockIdx.x*2048 + (bset*8 + i)*128 + o] = acc[i];
}

__global__ void k_reduce(const float* __restrict__ bout, float* __restrict__ out){
    int e = blockIdx.x*256 + threadIdx.x;   // 0..2047
    float s = bout[e & 127];
    #pragma unroll 8
    for (int c = 0; c < KCHUNKS_; c++) s += g_PART[c*2048 + e];
    out[e] = s;
}

// ---------------- launch ----------------
extern "C" void kernel_launch(void* const* d_in, const int* in_sizes, int n_in,
                              void* d_out, int out_size){
    const float* x    = (const float*)d_in[0];
    const float* prot = (const float*)d_in[1];
    const float* Wemb = (const float*)d_in[2];
    const float* bemb = (const float*)d_in[3];
    const float* Wpro = (const float*)d_in[4];
    const float* bpro = (const float*)d_in[5];
    const float* inw  = (const float*)d_in[6];
    const float* inb  = (const float*)d_in[7];
    const float* ow   = (const float*)d_in[8];
    const float* ob   = (const float*)d_in[9];
    const float* W1   = (const float*)d_in[10];
    const float* b1   = (const float*)d_in[11];
    const float* W2   = (const float*)d_in[12];
    const float* b2   = (const float*)d_in[13];
    const float* g1   = (const float*)d_in[14];
    const float* be1  = (const float*)d_in[15];
    const float* g2   = (const float*)d_in[16];
    const float* be2  = (const float*)d_in[17];
    const float* Wout = (const float*)d_in[18];
    const float* bout = (const float*)d_in[19];
    float* out = (float*)d_out;

    k_rowprep<<<1024, 256>>>(x, prot, Wemb, bemb, Wpro, bpro);
    k_mmagemm<0,0,128><<<dim3(TOK_/128, 2), 256>>>(0, inw, inb, 2, 128);
    k_mmagemm<0,1,128><<<dim3(KVN_/128, 4), 256>>>(0, inw + 128*E_, inb + 128, 3, 256);
    k_qnkmax<<<256 + B_*H_, 256>>>();
    k_attn<<<B_*H_*2, 256>>>();
    k_mmagemm<0,0,128><<<dim3(TOK_/128, 2), 256>>>(4, ow, ob, 5, 128);
    k_lnres<<<TOK_/8, 256>>>(0, 5, g1, be1, 6);
    k_mmagemm<1,0,128><<<dim3(TOK_/128, 1), 256>>>(6, W1, b1, 7, 64);
    k_mmagemm<0,0,64><<<dim3(TOK_/128, 2), 256>>>(7, W2, b2, 8, 128);
    k_lnres<<<TOK_/8, 256>>>(6, 8, g2, be2, 9);
    k_splitk<<<KCHUNKS_, 256>>>(Wout);
    k_reduce<<<8, 256>>>(bout, out);
}

// round 11
// speedup vs baseline: 2.1180x; 1.0427x over previous
#include <cuda_runtime.h>

// ---------------- problem constants ----------------
#define B_      16
#define N_      64
#define P_      6
#define D_      8
#define E_      128
#define H_      8
#define HD_     16
#define S_      512            // N*D tokens per batch
#define TOK_    (B_*S_)        // 8192
#define KVN_    (B_*2*S_)      // 16384
#define NPROTO_ 256            // D * 32 prototype rows
#define I_      64
#define O_      128
#define KOUT_   (S_*E_)        // 65536
#define KCHUNKS_ 256
#define KCSZ_   (KOUT_/KCHUNKS_) // 256

// ---------------- device scratch (no allocations allowed) ----------------
__device__ float g_IE  [TOK_*E_];
__device__ float g_PE  [TOK_*E_];
__device__ float g_Q   [TOK_*E_];
__device__ float g_KVO [KVN_*2*E_];   // cols 0..127 = K, 128..255 = V
__device__ float g_AT  [TOK_*E_];
__device__ float g_AP  [TOK_*E_];
__device__ float g_H1  [TOK_*E_];
__device__ float g_F1  [TOK_*I_];
__device__ float g_F2  [TOK_*E_];
__device__ float g_Z   [TOK_*E_];
__device__ float g_PART[KCHUNKS_*B_*O_];
__device__ float g_QN  [TOK_*H_];     // per (qrow, head) L2 norm
__device__ float g_KMAX[B_*H_];       // per (b, head) max key norm^2 (bits, atomicMax)

__device__ __forceinline__ float* bufptr(int id){
    switch(id){
        case 0: return g_IE;
        case 2: return g_Q;
        case 3: return g_KVO;
        case 4: return g_AT;
        case 5: return g_AP;
        case 6: return g_H1;
        case 7: return g_F1;
        case 8: return g_F2;
        default: return g_Z;
    }
}

// ---------------- tf32 helpers ----------------
__device__ __forceinline__ unsigned f2tf(float f){
    unsigned r; asm("cvt.rna.tf32.f32 %0, %1;" : "=r"(r) : "f"(f)); return r;
}
__device__ __forceinline__ void mma_tf32(float c[4], const unsigned a[4], const unsigned b[2]){
    asm volatile("mma.sync.aligned.m16n8k8.row.col.f32.tf32.tf32.f32 "
        "{%0,%1,%2,%3}, {%4,%5,%6,%7}, {%8,%9}, {%0,%1,%2,%3};"
        : "+f"(c[0]), "+f"(c[1]), "+f"(c[2]), "+f"(c[3])
        : "r"(a[0]), "r"(a[1]), "r"(a[2]), "r"(a[3]), "r"(b[0]), "r"(b[1]));
}

// ---------------- rowprep: proto inorm (in-block) + x inorm + argmax + embeds ----
__global__ void k_rowprep(const float* __restrict__ x, const float* __restrict__ proto,
                          const float* __restrict__ Wemb, const float* __restrict__ bemb,
                          const float* __restrict__ Wpro, const float* __restrict__ bpro){
    __shared__ float sPN  [NPROTO_*P_];
    __shared__ float sPNL2[NPROTO_*P_];
    __shared__ float sWe[E_*P_];
    __shared__ float sWp[E_*P_];
    __shared__ float sbe[E_];
    __shared__ float sbp[E_];
    int tid = threadIdx.x;
    if (blockIdx.x == 0 && tid < B_*H_) g_KMAX[tid] = 0.f;
    // prototype inorm + l2 (each block recomputes; 256 threads, 1 proto each)
    {
        float v[P_]; float s = 0.f;
        #pragma unroll
        for (int p = 0; p < P_; p++){ v[p] = proto[tid*P_ + p]; s += v[p]; }
        float m = s * (1.f/P_);
        float var = 0.f;
        #pragma unroll
        for (int p = 0; p < P_; p++){ float dd = v[p]-m; var += dd*dd; }
        var *= (1.f/P_);
        float rs = rsqrtf(var + 1e-5f);
        float nrm = 0.f;
        #pragma unroll
        for (int p = 0; p < P_; p++){ v[p] = (v[p]-m)*rs; nrm += v[p]*v[p]; sPN[tid*P_+p] = v[p]; }
        float inv = 1.f / fmaxf(sqrtf(nrm), 1e-12f);
        #pragma unroll
        for (int p = 0; p < P_; p++) sPNL2[tid*P_+p] = v[p]*inv;
    }
    for (int i = tid; i < E_*P_; i += 256){ sWe[i] = Wemb[i]; sWp[i] = Wpro[i]; }
    if (tid < E_){ sbe[tid] = bemb[tid]; sbp[tid] = bpro[tid]; }
    __syncthreads();

    int warp = tid >> 5, lane = tid & 31;
    int r = blockIdx.x*8 + warp;
    int b = r >> 9; int n = (r >> 3) & 63; int d = r & 7;
    const float* xp = x + ((b*64 + n)*6)*8 + d;

    float v[6]; float s = 0.f;
    #pragma unroll
    for (int p = 0; p < 6; p++){ v[p] = xp[p*8]; s += v[p]; }
    float mean = s * (1.f/6.f);
    float var = 0.f;
    #pragma unroll
    for (int p = 0; p < 6; p++){ float dd = v[p]-mean; var += dd*dd; }
    var *= (1.f/6.f);
    float rs = rsqrtf(var + 1e-5f);
    float xn[6];
    #pragma unroll
    for (int p = 0; p < 6; p++) xn[p] = (v[p]-mean)*rs;

    float best = -1e30f; int bi = 0;
    #pragma unroll
    for (int i = 0; i < 8; i++){
        int pidx = i*32 + lane;
        const float* pr = &sPNL2[pidx*6];
        float sim = xn[0]*pr[0] + xn[1]*pr[1] + xn[2]*pr[2]
                  + xn[3]*pr[3] + xn[4]*pr[4] + xn[5]*pr[5];
        if (sim > best){ best = sim; bi = pidx; }
    }
    #pragma unroll
    for (int off = 16; off; off >>= 1){
        float ov = __shfl_xor_sync(0xffffffffu, best, off);
        int   oi = __shfl_xor_sync(0xffffffffu, bi,   off);
        if (ov > best || (ov == best && oi < bi)){ best = ov; bi = oi; }
    }

    float sel[6];
    #pragma unroll
    for (int p = 0; p < 6; p++) sel[p] = sPN[bi*6 + p];

    #pragma unroll
    for (int e4 = 0; e4 < 4; e4++){
        int e = e4*32 + lane;
        const float* we = &sWe[e*6];
        const float* wp = &sWp[e*6];
        float a1 = sbe[e], a2 = sbp[e];
        #pragma unroll
        for (int p = 0; p < 6; p++){ a1 += xn[p]*we[p]; a2 += sel[p]*wp[p]; }
        g_IE[r*E_ + e] = a1;
        g_PE[r*E_ + e] = a2;
    }
}

// ---------------- tf32 tensor-core GEMM, fragment-major smem ------------------
// block 256 thr / 8 warps, tile 128M x 64N, warp 32x32.
// EPI: 0 = plain, 1 = per-head q-norm epilogue (-> g_QN), 2 = kmax epilogue.
template<int RELU, int CONCAT, int KK, int EPI>
__global__ void __launch_bounds__(256) k_mmagemm(int aId, const float* __restrict__ W,
                        const float* __restrict__ bias, int cId, int Nn){
    __shared__ __align__(16) unsigned sA[32*132];
    __shared__ __align__(16) unsigned sW[32*66];
    float* C = bufptr(cId);
    int t = threadIdx.x;
    int m0 = blockIdx.x * 128, n0 = blockIdx.y * 64;
    const float* Abase;
    if (CONCAT){
        int bb = m0 >> 10, j = m0 & 1023;
        Abase = ((j < 512) ? g_IE : g_PE) + (size_t)(bb*512 + (j & 511)) * KK;
    } else {
        Abase = bufptr(aId) + (size_t)m0 * KK;
    }
    int lane = t & 31, warp = t >> 5;
    int wm = warp >> 1, wn = warp & 1;
    int lq = lane >> 2, lc = lane & 3;
    int arow = t >> 3, ac4 = (t & 7)*4;
    int ksld = ac4 >> 3;
    int aslot = 2*((ac4 >> 2) & 1);
    int bslot = (ac4 >> 2) & 1;

    float c[2][4][4];
    #pragma unroll
    for (int mt = 0; mt < 2; mt++)
        #pragma unroll
        for (int nt = 0; nt < 4; nt++)
            c[mt][nt][0]=c[mt][nt][1]=c[mt][nt][2]=c[mt][nt][3]=0.f;

    float4 pa[4], pw[2];
    #pragma unroll
    for (int i = 0; i < 4; i++)
        pa[i] = *(const float4*)&Abase[(size_t)(arow + i*32)*KK + ac4];
    #pragma unroll
    for (int i = 0; i < 2; i++)
        pw[i] = *(const float4*)&W[(size_t)(n0 + arow + i*32)*KK + ac4];

    for (int k0 = 0; k0 < KK; k0 += 32){
        #pragma unroll
        for (int i = 0; i < 4; i++){
            int row = arow + i*32;
            int fa = (row >> 4)*4 + ksld;
            unsigned* d = &sA[fa*132 + (row & 7)*16 + ((row >> 3) & 1) + aslot];
            d[0]=f2tf(pa[i].x); d[4]=f2tf(pa[i].y); d[8]=f2tf(pa[i].z); d[12]=f2tf(pa[i].w);
        }
        #pragma unroll
        for (int i = 0; i < 2; i++){
            int row = arow + i*32;
            int fb = (row >> 3)*4 + ksld;
            unsigned* d = &sW[fb*66 + (row & 7)*8 + bslot];
            d[0]=f2tf(pw[i].x); d[2]=f2tf(pw[i].y); d[4]=f2tf(pw[i].z); d[6]=f2tf(pw[i].w);
        }
        __syncthreads();
        if (k0 + 32 < KK){
            #pragma unroll
            for (int i = 0; i < 4; i++)
                pa[i] = *(const float4*)&Abase[(size_t)(arow + i*32)*KK + k0 + 32 + ac4];
            #pragma unroll
            for (int i = 0; i < 2; i++)
                pw[i] = *(const float4*)&W[(size_t)(n0 + arow + i*32)*KK + k0 + 32 + ac4];
        }
        #pragma unroll
        for (int ks = 0; ks < 4; ks++){
            unsigned a[2][4], bf[4][2];
            #pragma unroll
            for (int mt = 0; mt < 2; mt++)
                *(uint4*)a[mt] = *(const uint4*)&sA[((2*wm + mt)*4 + ks)*132 + lane*4];
            #pragma unroll
            for (int nt = 0; nt < 4; nt++)
                *(uint2*)bf[nt] = *(const uint2*)&sW[((4*wn + nt)*4 + ks)*66 + lane*2];
            #pragma unroll
            for (int mt = 0; mt < 2; mt++)
                #pragma unroll
                for (int nt = 0; nt < 4; nt++)
                    mma_tf32(c[mt][nt], a[mt], bf[nt]);
        }
        __syncthreads();
    }
    #pragma unroll
    for (int nt = 0; nt < 4; nt++){
        int col = n0 + wn*32 + nt*8 + 2*lc;
        float b0 = bias[col], b1 = bias[col+1];
        #pragma unroll
        for (int mt = 0; mt < 2; mt++){
            int row = m0 + wm*32 + mt*16 + lq;
            float v0 = c[mt][nt][0] + b0, v1 = c[mt][nt][1] + b1;
            float v2 = c[mt][nt][2] + b0, v3 = c[mt][nt][3] + b1;
            if (RELU){
                v0 = fmaxf(v0,0.f); v1 = fmaxf(v1,0.f);
                v2 = fmaxf(v2,0.f); v3 = fmaxf(v3,0.f);
            }
            *(float2*)&C[(size_t)row*Nn + col]     = make_float2(v0, v1);
            *(float2*)&C[(size_t)(row+8)*Nn + col] = make_float2(v2, v3);
            c[mt][nt][0]=v0; c[mt][nt][1]=v1; c[mt][nt][2]=v2; c[mt][nt][3]=v3;
        }
    }
    if (EPI == 1){
        // per-head (16-col) L2 norm of q rows -> g_QN
        #pragma unroll
        for (int p = 0; p < 2; p++){
            int head = (n0 >> 4) + wn*2 + p;
            #pragma unroll
            for (int mt = 0; mt < 2; mt++){
                float s0 = 0.f, s1 = 0.f;
                #pragma unroll
                for (int q = 0; q < 2; q++){
                    int nt = 2*p + q;
                    s0 += c[mt][nt][0]*c[mt][nt][0] + c[mt][nt][1]*c[mt][nt][1];
                    s1 += c[mt][nt][2]*c[mt][nt][2] + c[mt][nt][3]*c[mt][nt][3];
                }
                s0 += __shfl_xor_sync(0xffffffffu, s0, 1);
                s0 += __shfl_xor_sync(0xffffffffu, s0, 2);
                s1 += __shfl_xor_sync(0xffffffffu, s1, 1);
                s1 += __shfl_xor_sync(0xffffffffu, s1, 2);
                if (lc == 0){
                    int row = m0 + wm*32 + mt*16 + lq;
                    g_QN[row*8 + head]     = sqrtf(s0);
                    g_QN[(row+8)*8 + head] = sqrtf(s1);
                }
            }
        }
    }
    if (EPI == 2 && n0 < 128){
        // per-head max key norm^2 over this block's 128 rows -> atomicMax g_KMAX
        int bb = m0 >> 10;
        #pragma unroll
        for (int p = 0; p < 2; p++){
            int head = (n0 >> 4) + wn*2 + p;
            float mx = 0.f;
            #pragma unroll
            for (int mt = 0; mt < 2; mt++){
                float s0 = 0.f, s1 = 0.f;
                #pragma unroll
                for (int q = 0; q < 2; q++){
                    int nt = 2*p + q;
                    s0 += c[mt][nt][0]*c[mt][nt][0] + c[mt][nt][1]*c[mt][nt][1];
                    s1 += c[mt][nt][2]*c[mt][nt][2] + c[mt][nt][3]*c[mt][nt][3];
                }
                s0 += __shfl_xor_sync(0xffffffffu, s0, 1);
                s0 += __shfl_xor_sync(0xffffffffu, s0, 2);
                s1 += __shfl_xor_sync(0xffffffffu, s1, 1);
                s1 += __shfl_xor_sync(0xffffffffu, s1, 2);
                mx = fmaxf(mx, fmaxf(s0, s1));
            }
            #pragma unroll
            for (int off = 16; off; off >>= 1)
                mx = fmaxf(mx, __shfl_xor_sync(0xffffffffu, mx, off));
            if (lane == 0)
                atomicMax((unsigned*)&g_KMAX[bb*8 + head], __float_as_uint(mx));
        }
    }
}

// ---------------- attention: 8 warps/block, 32-key smem tiles -----------------
__global__ void __launch_bounds__(256) k_attn(){
    __shared__ float sK[32*20];
    __shared__ float sV[32*24];
    int blk = blockIdx.x;                 // 0..255
    int bh = blk >> 1, qh = blk & 1;
    int b = bh >> 3, h = bh & 7;
    int t = threadIdx.x;
    int lane = t & 31, warp = t >> 5;
    int lq = lane >> 2, lc = lane & 3;
    int qrow0 = b*512 + qh*256 + warp*32;
    int hoff = h*16;
    const float* Qb  = g_Q  + (size_t)qrow0*E_ + hoff;
    const float* KVb = g_KVO + (size_t)(b*1024)*256;

    unsigned qa[2][2][4];
    #pragma unroll
    for (int mt = 0; mt < 2; mt++)
        #pragma unroll
        for (int ks = 0; ks < 2; ks++){
            const float* qp = Qb + (size_t)(mt*16)*E_ + ks*8;
            qa[mt][ks][0] = f2tf(qp[(size_t)lq*E_     + lc]);
            qa[mt][ks][1] = f2tf(qp[(size_t)(lq+8)*E_ + lc]);
            qa[mt][ks][2] = f2tf(qp[(size_t)lq*E_     + lc+4]);
            qa[mt][ks][3] = f2tf(qp[(size_t)(lq+8)*E_ + lc+4]);
        }

    float kmax = sqrtf(g_KMAX[bh]);
    float mb[2][2];
    #pragma unroll
    for (int mt = 0; mt < 2; mt++){
        mb[mt][0] = g_QN[(qrow0 + mt*16 + lq  )*8 + h] * kmax * 0.25f;
        mb[mt][1] = g_QN[(qrow0 + mt*16 + lq+8)*8 + h] * kmax * 0.25f;
    }

    float o[2][2][4];
    #pragma unroll
    for (int mt = 0; mt < 2; mt++)
        #pragma unroll
        for (int d = 0; d < 2; d++)
            o[mt][d][0]=o[mt][d][1]=o[mt][d][2]=o[mt][d][3]=0.f;
    float lsum[2][2] = {};

    int s1 = (lane & 28) | (lc >> 1);
    int s2 = s1 + 2;
    bool odd = lc & 1;

    int sj = t >> 3, sf = t & 7;          // 32 rows x 8 quarters
    int scol = (sf & 3)*4;

    #pragma unroll 1
    for (int key0 = 0; key0 < 1024; key0 += 32){
        {
            const float* src = KVb + (size_t)(key0 + sj)*256 +
                               ((sf < 4) ? (hoff + scol) : (128 + hoff + scol));
            float4 v = *(const float4*)src;
            float* dst = (sf < 4) ? &sK[sj*20 + scol] : &sV[sj*24 + scol];
            *(float4*)dst = v;
        }
        __syncthreads();

        #pragma unroll
        for (int sub = 0; sub < 2; sub++){
            int r16 = sub*16;
            unsigned kb[2][2][2];
            #pragma unroll
            for (int nt = 0; nt < 2; nt++)
                #pragma unroll
                for (int ks = 0; ks < 2; ks++){
                    const float* kp = &sK[(r16 + nt*8 + lq)*20 + ks*8 + lc];
                    kb[nt][ks][0] = f2tf(kp[0]);
                    kb[nt][ks][1] = f2tf(kp[4]);
                }
            float s[2][2][4];
            #pragma unroll
            for (int mt = 0; mt < 2; mt++)
                #pragma unroll
                for (int nt = 0; nt < 2; nt++){
                    s[mt][nt][0]=s[mt][nt][1]=s[mt][nt][2]=s[mt][nt][3]=0.f;
                    mma_tf32(s[mt][nt], qa[mt][0], kb[nt][0]);
                    mma_tf32(s[mt][nt], qa[mt][1], kb[nt][1]);
                }
            #pragma unroll
            for (int mt = 0; mt < 2; mt++)
                #pragma unroll
                for (int nt = 0; nt < 2; nt++){
                    float p0 = __expf(s[mt][nt][0]*0.25f - mb[mt][0]);
                    float p1 = __expf(s[mt][nt][1]*0.25f - mb[mt][0]);
                    float p2 = __expf(s[mt][nt][2]*0.25f - mb[mt][1]);
                    float p3 = __expf(s[mt][nt][3]*0.25f - mb[mt][1]);
                    float q0 = __uint_as_float(f2tf(p0));
                    float q1 = __uint_as_float(f2tf(p1));
                    float q2 = __uint_as_float(f2tf(p2));
                    float q3 = __uint_as_float(f2tf(p3));
                    s[mt][nt][0]=q0; s[mt][nt][1]=q1; s[mt][nt][2]=q2; s[mt][nt][3]=q3;
                    lsum[mt][0] += q0 + q1;
                    lsum[mt][1] += q2 + q3;
                }
            unsigned vb[2][2][2];
            #pragma unroll
            for (int kt = 0; kt < 2; kt++)
                #pragma unroll
                for (int d = 0; d < 2; d++){
                    const float* vp = &sV[(r16 + kt*8 + lc)*24 + d*8 + lq];
                    vb[kt][d][0] = f2tf(vp[0]);
                    vb[kt][d][1] = f2tf(vp[4*24]);
                }
            #pragma unroll
            for (int mt = 0; mt < 2; mt++)
                #pragma unroll
                for (int kt = 0; kt < 2; kt++){
                    unsigned a[4];
                    float w0 = __shfl_sync(0xffffffffu, s[mt][kt][0], s1);
                    float w1 = __shfl_sync(0xffffffffu, s[mt][kt][1], s1);
                    a[0] = __float_as_uint(odd ? w1 : w0);
                    float w2 = __shfl_sync(0xffffffffu, s[mt][kt][2], s1);
                    float w3 = __shfl_sync(0xffffffffu, s[mt][kt][3], s1);
                    a[1] = __float_as_uint(odd ? w3 : w2);
                    w0 = __shfl_sync(0xffffffffu, s[mt][kt][0], s2);
                    w1 = __shfl_sync(0xffffffffu, s[mt][kt][1], s2);
                    a[2] = __float_as_uint(odd ? w1 : w0);
                    w2 = __shfl_sync(0xffffffffu, s[mt][kt][2], s2);
                    w3 = __shfl_sync(0xffffffffu, s[mt][kt][3], s2);
                    a[3] = __float_as_uint(odd ? w3 : w2);
                    mma_tf32(o[mt][0], a, vb[kt][0]);
                    mma_tf32(o[mt][1], a, vb[kt][1]);
                }
        }
        __syncthreads();
    }

    float inv[2][2];
    #pragma unroll
    for (int mt = 0; mt < 2; mt++)
        #pragma unroll
        for (int hf = 0; hf < 2; hf++){
            float l = lsum[mt][hf];
            l += __shfl_xor_sync(0xffffffffu, l, 1);
            l += __shfl_xor_sync(0xffffffffu, l, 2);
            inv[mt][hf] = 1.f / l;
        }
    #pragma unroll
    for (int mt = 0; mt < 2; mt++)
        #pragma unroll
        for (int d = 0; d < 2; d++){
            float* op = g_AT + (size_t)(qrow0 + mt*16 + lq)*E_ + hoff + d*8 + 2*lc;
            *(float2*)op = make_float2(o[mt][d][0]*inv[mt][0], o[mt][d][1]*inv[mt][0]);
            *(float2*)(op + 8*E_) = make_float2(o[mt][d][2]*inv[mt][1], o[mt][d][3]*inv[mt][1]);
        }
}

// ---------------- residual + LayerNorm (row = 128) ----------------
__global__ void k_lnres(int aId, int rId, const float* __restrict__ g,
                        const float* __restrict__ be, int oId){
    const float* A = bufptr(aId);
    const float* R = bufptr(rId);
    float* out = bufptr(oId);
    int tid = threadIdx.x; int warp = tid >> 5, lane = tid & 31;
    int row = blockIdx.x*8 + warp;
    float v[4];
    #pragma unroll
    for (int i = 0; i < 4; i++){
        int e = i*32 + lane;
        v[i] = A[(size_t)row*E_ + e] + R[(size_t)row*E_ + e];
    }
    float s  = v[0]+v[1]+v[2]+v[3];
    float s2 = v[0]*v[0]+v[1]*v[1]+v[2]*v[2]+v[3]*v[3];
    #pragma unroll
    for (int off = 16; off; off >>= 1){
        s  += __shfl_xor_sync(0xffffffffu, s,  off);
        s2 += __shfl_xor_sync(0xffffffffu, s2, off);
    }
    float mean = s * (1.f/128.f);
    float var  = s2 * (1.f/128.f) - mean*mean;
    float rs = rsqrtf(var + 1e-5f);
    #pragma unroll
    for (int i = 0; i < 4; i++){
        int e = i*32 + lane;
        out[(size_t)row*E_ + e] = (v[i]-mean)*rs*g[e] + be[e];
    }
}

// ---------------- final projection: split-K over 65536 (fp32) -----------------
__global__ void k_splitk(const float* __restrict__ W){
    __shared__ float Zs[16*32];
    __shared__ float Ws_[32*129];
    int t = threadIdx.x;
    int kb = blockIdx.x * KCSZ_;
    int o = t & 127;
    int bset = t >> 7;
    float acc[8];
    #pragma unroll
    for (int i = 0; i < 8; i++) acc[i] = 0.f;
    for (int k0 = 0; k0 < KCSZ_; k0 += 32){
        #pragma unroll
        for (int i = 0; i < 2; i++){
            int e = t + i*256; int b_ = e >> 5, kk = e & 31;
            Zs[b_*32 + kk] = g_Z[(size_t)b_*KOUT_ + kb + k0 + kk];
        }
        #pragma unroll
        for (int i = 0; i < 16; i++){
            int e = t + i*256; int oo = e >> 5, kk = e & 31;
            Ws_[kk*129 + oo] = W[(size_t)oo*KOUT_ + kb + k0 + kk];
        }
        __syncthreads();
        #pragma unroll
        for (int kk = 0; kk < 32; kk++){
            float w = Ws_[kk*129 + o];
            #pragma unroll
            for (int i = 0; i < 8; i++)
                acc[i] += Zs[(bset*8 + i)*32 + kk] * w;
        }
        __syncthreads();
    }
    #pragma unroll
    for (int i = 0; i < 8; i++)
        g_PART[blockIdx.x*2048 + (bset*8 + i)*128 + o] = acc[i];
}

__global__ void k_reduce(const float* __restrict__ bout, float* __restrict__ out){
    int e = blockIdx.x*256 + threadIdx.x;   // 0..2047
    float s = bout[e & 127];
    #pragma unroll 8
    for (int c = 0; c < KCHUNKS_; c++) s += g_PART[c*2048 + e];
    out[e] = s;
}

// ---------------- launch ----------------
extern "C" void kernel_launch(void* const* d_in, const int* in_sizes, int n_in,
                              void* d_out, int out_size){
    const float* x    = (const float*)d_in[0];
    const float* prot = (const float*)d_in[1];
    const float* Wemb = (const float*)d_in[2];
    const float* bemb = (const float*)d_in[3];
    const float* Wpro = (const float*)d_in[4];
    const float* bpro = (const float*)d_in[5];
    const float* inw  = (const float*)d_in[6];
    const float* inb  = (const float*)d_in[7];
    const float* ow   = (const float*)d_in[8];
    const float* ob   = (const float*)d_in[9];
    const float* W1   = (const float*)d_in[10];
    const float* b1   = (const float*)d_in[11];
    const float* W2   = (const float*)d_in[12];
    const float* b2   = (const float*)d_in[13];
    const float* g1   = (const float*)d_in[14];
    const float* be1  = (const float*)d_in[15];
    const float* g2   = (const float*)d_in[16];
    const float* be2  = (const float*)d_in[17];
    const float* Wout = (const float*)d_in[18];
    const float* bout = (const float*)d_in[19];
    float* out = (float*)d_out;

    k_rowprep<<<1024, 256>>>(x, prot, Wemb, bemb, Wpro, bpro);
    // Q projection + q-norm epilogue
    k_mmagemm<0,0,128,1><<<dim3(TOK_/128, 2), 256>>>(0, inw, inb, 2, 128);
    // K|V projection (virtual concat) + kmax epilogue
    k_mmagemm<0,1,128,2><<<dim3(KVN_/128, 4), 256>>>(0, inw + 128*E_, inb + 128, 3, 256);
    k_attn<<<B_*H_*2, 256>>>();
    k_mmagemm<0,0,128,0><<<dim3(TOK_/128, 2), 256>>>(4, ow, ob, 5, 128);
    k_lnres<<<TOK_/8, 256>>>(0, 5, g1, be1, 6);
    k_mmagemm<1,0,128,0><<<dim3(TOK_/128, 1), 256>>>(6, W1, b1, 7, 64);
    k_mmagemm<0,0,64,0><<<dim3(TOK_/128, 2), 256>>>(7, W2, b2, 8, 128);
    k_lnres<<<TOK_/8, 256>>>(6, 8, g2, be2, 9);
    k_splitk<<<KCHUNKS_, 256>>>(Wout);
    k_reduce<<<8, 256>>>(bout, out);
}